// round 11
// baseline (speedup 1.0000x reference)
#include <cuda_runtime.h>
#include <cuda_fp16.h>
#include <mma.h>

using namespace nvcuda;

#define MAXN 100000
#define MAXE 1600000
#define MAXL 8

// Persistent scratch (no allocations allowed).
__device__ float4 g_hh4[MAXN * 8];     // h hi (half, N x 64)
__device__ float4 g_hl4[MAXN * 8];     // h lo
__device__ float4 g_Mh4[MAXN * 8];     // M'' (fp16, N x 64)
__device__ float4 g_agg4f[(MAXN + 128) * 16];  // agg'' (fp32, N x 64)
__device__ float4 g_wh4[MAXL * 2048];  // weights hi: 16384 half / layer
__device__ float4 g_wl4[MAXL * 2048];  // weights lo: 16384 half / layer
__device__ float g_cb[MAXL * 64];      // fused bias c = b2 @ updW1b
// CSR
__device__ int g_counts[MAXN];
__device__ int g_rowstart[MAXN];
__device__ int g_rowend[MAXN];
__device__ int g_csrsrc[MAXE];
__device__ int g_blocksum[128];

__device__ __forceinline__ void split2(float x, __half& hi, __half& lo) {
  hi = __float2half_rn(x);
  lo = __float2half_rn(x - __half2float(hi));
}

// ---------------------------------------------------------------------------
// wprep_split: copy+split msgW1 -> [0,4096), updW1a -> [8192,12288),
// updW2 -> [12288,16384). (V fills [4096,8192) in wprep_fuse.)
// ---------------------------------------------------------------------------
__global__ void __launch_bounds__(256) wprep_split_kernel(
    const float* __restrict__ mw1, const float* __restrict__ uw1,
    const float* __restrict__ uw2, int L) {
  int i = blockIdx.x * blockDim.x + threadIdx.x;
  if (i >= L * 12288) return;
  int l = i / 12288, off = i % 12288;
  int seg = off >> 12, r = off & 4095;
  float v;
  int dst;
  if (seg == 0) {
    v = __ldg(mw1 + l * 4096 + r);
    dst = l * 16384 + r;
  } else if (seg == 1) {
    v = __ldg(uw1 + l * 8192 + r);  // rows [0,64) = W1a
    dst = l * 16384 + 8192 + r;
  } else {
    v = __ldg(uw2 + l * 4096 + r);
    dst = l * 16384 + 12288 + r;
  }
  __half hi, lo;
  split2(v, hi, lo);
  ((__half*)g_wh4)[dst] = hi;
  ((__half*)g_wl4)[dst] = lo;
}

// ---------------------------------------------------------------------------
// wprep_fuse: V = msgW2 @ updW1b (64x64, fp32), c = msg_b2 @ updW1b.
// One block per layer.
// ---------------------------------------------------------------------------
__global__ void __launch_bounds__(256) wprep_fuse_kernel(
    const float* __restrict__ mw2, const float* __restrict__ uw1,
    const float* __restrict__ mb2) {
  __shared__ float su[4096];  // updW1b (rows [64,128) of uw1)
  __shared__ float sw[4096];  // msgW2
  int l = blockIdx.x, t = threadIdx.x;
  for (int i = t; i < 4096; i += 256) {
    su[i] = __ldg(uw1 + l * 8192 + 4096 + i);
    sw[i] = __ldg(mw2 + l * 4096 + i);
  }
  __syncthreads();
  for (int e = t; e < 4096; e += 256) {
    int k = e >> 6, n = e & 63;
    float s = 0.f;
#pragma unroll 8
    for (int j = 0; j < 64; j++) s += sw[k * 64 + j] * su[j * 64 + n];
    __half hi, lo;
    split2(s, hi, lo);
    ((__half*)g_wh4)[l * 16384 + 4096 + e] = hi;
    ((__half*)g_wl4)[l * 16384 + 4096 + e] = lo;
  }
  if (t < 64) {
    float s = 0.f;
#pragma unroll 8
    for (int j = 0; j < 64; j++) s += __ldg(mb2 + l * 64 + j) * su[j * 64 + t];
    g_cb[l * 64 + t] = s;
  }
}

// ---------------------------------------------------------------------------
// h = relu(x @ w_in + b_in), stored split
// ---------------------------------------------------------------------------
__global__ void __launch_bounds__(256) input_kernel(
    const float* __restrict__ x, const float* __restrict__ w_in,
    const float* __restrict__ b_in, int N) {
  int i = blockIdx.x * blockDim.x + threadIdx.x;
  if (i >= N * 64) return;
  int node = i >> 6, c = i & 63;
  float acc = __ldg(b_in + c);
  acc = fmaf(__ldg(x + node * 3 + 0), __ldg(w_in + c), acc);
  acc = fmaf(__ldg(x + node * 3 + 1), __ldg(w_in + 64 + c), acc);
  acc = fmaf(__ldg(x + node * 3 + 2), __ldg(w_in + 128 + c), acc);
  float h = fmaxf(acc, 0.f);
  __half hi, lo;
  split2(h, hi, lo);
  ((__half*)g_hh4)[i] = hi;
  ((__half*)g_hl4)[i] = lo;
}

// ---------------------------------------------------------------------------
// CSR build
// ---------------------------------------------------------------------------
__global__ void __launch_bounds__(256) zero_counts_kernel(int N) {
  int i = blockIdx.x * blockDim.x + threadIdx.x;
  if (i < N) g_counts[i] = 0;
}

__global__ void __launch_bounds__(256) hist_kernel(const int* __restrict__ ei,
                                                   int E) {
  int e = blockIdx.x * blockDim.x + threadIdx.x;
  if (e < E) atomicAdd(&g_counts[__ldg(ei + E + e)], 1);
}

__global__ void __launch_bounds__(1024) scan1_kernel(int N) {
  __shared__ int sh[1024];
  int t = threadIdx.x;
  int idx = blockIdx.x * 1024 + t;
  int v = (idx < N) ? g_counts[idx] : 0;
  sh[t] = v;
  __syncthreads();
#pragma unroll
  for (int off = 1; off < 1024; off <<= 1) {
    int x = (t >= off) ? sh[t - off] : 0;
    __syncthreads();
    sh[t] += x;
    __syncthreads();
  }
  if (idx < N) g_rowstart[idx] = sh[t] - v;
  if (t == 1023) g_blocksum[blockIdx.x] = sh[1023];
}

__global__ void __launch_bounds__(128) scan2_kernel(int nb) {
  __shared__ int sh[128];
  int t = threadIdx.x;
  int v = (t < nb) ? g_blocksum[t] : 0;
  sh[t] = v;
  __syncthreads();
#pragma unroll
  for (int off = 1; off < 128; off <<= 1) {
    int x = (t >= off) ? sh[t - off] : 0;
    __syncthreads();
    sh[t] += x;
    __syncthreads();
  }
  if (t < nb) g_blocksum[t] = sh[t] - v;
}

__global__ void __launch_bounds__(256) scan3_kernel(int N) {
  int i = blockIdx.x * blockDim.x + threadIdx.x;
  if (i < N) {
    int v = g_rowstart[i] + g_blocksum[i >> 10];
    g_rowstart[i] = v;
    g_rowend[i] = v;
  }
}

__global__ void __launch_bounds__(256) fill_kernel(const int* __restrict__ ei,
                                                   int E) {
  int e = blockIdx.x * blockDim.x + threadIdx.x;
  if (e < E) {
    int d = __ldg(ei + E + e);
    int pos = atomicAdd(&g_rowend[d], 1);
    g_csrsrc[pos] = __ldg(ei + e);
  }
}

// ---------------------------------------------------------------------------
// agg''[i] = sum_{e: dst(e)=i} M''[src(e)]  (warp/node, fp32 out, MLP=4)
// ---------------------------------------------------------------------------
__global__ void __launch_bounds__(256) gather_kernel(int N) {
  int w = (blockIdx.x * blockDim.x + threadIdx.x) >> 5;
  int lane = threadIdx.x & 31;
  if (w >= N) return;
  int s = __ldg(&g_rowstart[w]);
  int e = __ldg(&g_rowend[w]);
  const __half2* M = (const __half2*)g_Mh4;
  float2 a0 = make_float2(0.f, 0.f), a1 = make_float2(0.f, 0.f);
  float2 a2 = make_float2(0.f, 0.f), a3 = make_float2(0.f, 0.f);
  int j = s;
  for (; j + 4 <= e; j += 4) {
    int s0 = __ldg(&g_csrsrc[j]);
    int s1 = __ldg(&g_csrsrc[j + 1]);
    int s2 = __ldg(&g_csrsrc[j + 2]);
    int s3 = __ldg(&g_csrsrc[j + 3]);
    float2 v0 = __half22float2(__ldg(&M[(size_t)s0 * 32 + lane]));
    float2 v1 = __half22float2(__ldg(&M[(size_t)s1 * 32 + lane]));
    float2 v2 = __half22float2(__ldg(&M[(size_t)s2 * 32 + lane]));
    float2 v3 = __half22float2(__ldg(&M[(size_t)s3 * 32 + lane]));
    a0.x += v0.x; a0.y += v0.y;
    a1.x += v1.x; a1.y += v1.y;
    a2.x += v2.x; a2.y += v2.y;
    a3.x += v3.x; a3.y += v3.y;
  }
  for (; j < e; j++) {
    int s0 = __ldg(&g_csrsrc[j]);
    float2 v0 = __half22float2(__ldg(&M[(size_t)s0 * 32 + lane]));
    a0.x += v0.x; a0.y += v0.y;
  }
  ((float2*)g_agg4f)[(size_t)w * 32 + lane] =
      make_float2((a0.x + a1.x) + (a2.x + a3.x),
                  (a0.y + a1.y) + (a2.y + a3.y));
}

// 3-term split MMA, 32x32 warp tile (2x2 16x16 frags), one 16-k chunk.
#define MMA_STEP32(APH, APL, BPH, BPL)                                       \
  {                                                                          \
    wmma::fragment<wmma::matrix_a, 16, 16, 16, __half, wmma::row_major>    \
        ah0, ah1, al0, al1;                                                  \
    wmma::fragment<wmma::matrix_b, 16, 16, 16, __half, wmma::row_major>    \
        bh0, bh1, bl0, bl1;                                                  \
    wmma::load_matrix_sync(ah0, (APH), 72);                                  \
    wmma::load_matrix_sync(ah1, (APH) + 16 * 72, 72);                        \
    wmma::load_matrix_sync(al0, (APL), 72);                                  \
    wmma::load_matrix_sync(al1, (APL) + 16 * 72, 72);                        \
    wmma::load_matrix_sync(bh0, (BPH), 72);                                  \
    wmma::load_matrix_sync(bh1, (BPH) + 16, 72);                             \
    wmma::load_matrix_sync(bl0, (BPL), 72);                                  \
    wmma::load_matrix_sync(bl1, (BPL) + 16, 72);                             \
    wmma::mma_sync(acc00, ah0, bh0, acc00);                                  \
    wmma::mma_sync(acc00, al0, bh0, acc00);                                  \
    wmma::mma_sync(acc00, ah0, bl0, acc00);                                  \
    wmma::mma_sync(acc01, ah0, bh1, acc01);                                  \
    wmma::mma_sync(acc01, al0, bh1, acc01);                                  \
    wmma::mma_sync(acc01, ah0, bl1, acc01);                                  \
    wmma::mma_sync(acc10, ah1, bh0, acc10);                                  \
    wmma::mma_sync(acc10, al1, bh0, acc10);                                  \
    wmma::mma_sync(acc10, ah1, bl0, acc10);                                  \
    wmma::mma_sync(acc11, ah1, bh1, acc11);                                  \
    wmma::mma_sync(acc11, al1, bh1, acc11);                                  \
    wmma::mma_sync(acc11, ah1, bl1, acc11);                                  \
  }

#define STORE_ACC32()                                                        \
  {                                                                          \
    wmma::store_matrix_sync(fs + wr * 72 + wc, acc00, 72,                    \
                            wmma::mem_row_major);                            \
    wmma::store_matrix_sync(fs + wr * 72 + wc + 16, acc01, 72,               \
                            wmma::mem_row_major);                            \
    wmma::store_matrix_sync(fs + (wr + 16) * 72 + wc, acc10, 72,             \
                            wmma::mem_row_major);                            \
    wmma::store_matrix_sync(fs + (wr + 16) * 72 + wc + 16, acc11, 72,        \
                            wmma::mem_row_major);                            \
  }

#define FILL_ACC32()                                                         \
  {                                                                          \
    wmma::fill_fragment(acc00, 0.f);                                         \
    wmma::fill_fragment(acc01, 0.f);                                         \
    wmma::fill_fragment(acc10, 0.f);                                         \
    wmma::fill_fragment(acc11, 0.f);                                         \
  }

// Common staging: W1 (wh+0), W2 (wh+4096), A = split h. 128-row tile.
#define STAGE_COMMON()                                                       \
  for (int j = tid; j < 512; j += 256) {                                     \
    int k = j >> 3, ch = j & 7;                                              \
    *(uint4*)((char*)w1h + k * 144 + ch * 16) = __ldg((const uint4*)wh + j); \
    *(uint4*)((char*)w1l + k * 144 + ch * 16) = __ldg((const uint4*)wl + j); \
    *(uint4*)((char*)w2h + k * 144 + ch * 16) =                              \
        __ldg((const uint4*)(wh + 4096) + j);                                \
    *(uint4*)((char*)w2l + k * 144 + ch * 16) =                              \
        __ldg((const uint4*)(wl + 4096) + j);                                \
  }                                                                          \
  for (int j = tid; j < 1024; j += 256) {                                    \
    int r = j >> 3, ch = j & 7;                                              \
    int grow = rb + r;                                                       \
    uint4 vh = make_uint4(0, 0, 0, 0), vl = make_uint4(0, 0, 0, 0);          \
    if (grow < N) {                                                          \
      vh = __ldg((const uint4*)((const char*)g_hh4 + (size_t)grow * 128) +   \
                 ch);                                                        \
      vl = __ldg((const uint4*)((const char*)g_hl4 + (size_t)grow * 128) +   \
                 ch);                                                        \
    }                                                                        \
    *(uint4*)((char*)a_hi + r * 144 + ch * 16) = vh;                         \
    *(uint4*)((char*)a_lo + r * 144 + ch * 16) = vl;                         \
  }

// ---------------------------------------------------------------------------
// msg: M'' = relu(h @ W1 + b1) @ V + c.   128-row tile, 4 barriers.
// ---------------------------------------------------------------------------
__global__ void __launch_bounds__(256) msg_kernel(
    const __half* __restrict__ wh, const __half* __restrict__ wl,
    const float* __restrict__ B1, const float* __restrict__ CB, int N) {
  extern __shared__ char smc[];
  __half* a_hi = (__half*)smc;       // 128 x 72
  __half* a_lo = a_hi + 128 * 72;
  __half* w1h = a_lo + 128 * 72;     // 64 x 72
  __half* w1l = w1h + 64 * 72;
  __half* w2h = w1l + 64 * 72;       // V
  __half* w2l = w2h + 64 * 72;
  float* fs = (float*)(w2l + 64 * 72);  // 128 x 72
  __shared__ float sb1[64], sb2[64];

  int tid = threadIdx.x;
  int rb = blockIdx.x * 128;

  STAGE_COMMON();
  if (tid < 64) {
    sb1[tid] = __ldg(B1 + tid);
    sb2[tid] = __ldg(CB + tid);
  }
  __syncthreads();

  int wid = tid >> 5;
  int wr = (wid & 3) * 32, wc = (wid >> 2) * 32;

  wmma::fragment<wmma::accumulator, 16, 16, 16, float> acc00, acc01, acc10,
      acc11;
  FILL_ACC32();
#pragma unroll
  for (int k = 0; k < 64; k += 16)
    MMA_STEP32(a_hi + wr * 72 + k, a_lo + wr * 72 + k, w1h + k * 72 + wc,
               w1l + k * 72 + wc);
  STORE_ACC32();
  __syncthreads();

  // t = relu(fs + b1) -> a buffers (split)
  {
    int r = tid >> 1, c0 = (tid & 1) * 32;
#pragma unroll
    for (int q = 0; q < 8; q++) {
      int c = c0 + q * 4;
      float4 v = *(const float4*)(fs + r * 72 + c);
      float t0 = fmaxf(v.x + sb1[c + 0], 0.f);
      float t1 = fmaxf(v.y + sb1[c + 1], 0.f);
      float t2 = fmaxf(v.z + sb1[c + 2], 0.f);
      float t3 = fmaxf(v.w + sb1[c + 3], 0.f);
      __half h0, l0, h1, l1, h2, l2, h3, l3;
      split2(t0, h0, l0); split2(t1, h1, l1);
      split2(t2, h2, l2); split2(t3, h3, l3);
      *(__half2*)(a_hi + r * 72 + c) = __halves2half2(h0, h1);
      *(__half2*)(a_hi + r * 72 + c + 2) = __halves2half2(h2, h3);
      *(__half2*)(a_lo + r * 72 + c) = __halves2half2(l0, l1);
      *(__half2*)(a_lo + r * 72 + c + 2) = __halves2half2(l2, l3);
    }
  }
  __syncthreads();

  FILL_ACC32();
#pragma unroll
  for (int k = 0; k < 64; k += 16)
    MMA_STEP32(a_hi + wr * 72 + k, a_lo + wr * 72 + k, w2h + k * 72 + wc,
               w2l + k * 72 + wc);
  STORE_ACC32();
  __syncthreads();

  // M'' = fs + c  (fp16, straight to global)
  {
    int r = tid >> 1, c0 = (tid & 1) * 32;
    int grow = rb + r;
    if (grow < N) {
      __half* mp = (__half*)g_Mh4 + (size_t)grow * 64 + c0;
#pragma unroll
      for (int q = 0; q < 8; q++) {
        int c = c0 + q * 4;
        float4 v = *(const float4*)(fs + r * 72 + c);
        *(__half2*)(mp + q * 4) =
            __floats2half2_rn(v.x + sb2[c + 0], v.y + sb2[c + 1]);
        *(__half2*)(mp + q * 4 + 2) =
            __floats2half2_rn(v.z + sb2[c + 2], v.w + sb2[c + 3]);
      }
    }
  }
}

// ---------------------------------------------------------------------------
// upd: t = relu(h @ W1a + agg'' + b1); hn = t @ W2 + b2; bn; h = relu(hn+h)
// 128-row tile, identical shape to msg. agg'' read fp32 from global;
// residual h_old read fp32-exact (hi+lo) from global at epilogue.
// ---------------------------------------------------------------------------
__global__ void __launch_bounds__(256) upd_kernel(
    const __half* __restrict__ wh, const __half* __restrict__ wl,
    const float* __restrict__ B1, const float* __restrict__ B2,
    const float* __restrict__ Gm, const float* __restrict__ Bt,
    const float* __restrict__ Mn, const float* __restrict__ Vr, int N) {
  extern __shared__ char smc[];
  __half* a_hi = (__half*)smc;       // 128 x 72
  __half* a_lo = a_hi + 128 * 72;
  __half* w1h = a_lo + 128 * 72;     // W1a 64 x 72
  __half* w1l = w1h + 64 * 72;
  __half* w2h = w1l + 64 * 72;       // W2 64 x 72
  __half* w2l = w2h + 64 * 72;
  float* fs = (float*)(w2l + 64 * 72);  // 128 x 72
  __shared__ float sb1[64], b2s[64], scs[64], shs[64];

  int tid = threadIdx.x;
  int rb = blockIdx.x * 128;

  STAGE_COMMON();
  if (tid < 64) {
    float s = __ldg(Gm + tid) * rsqrtf(__ldg(Vr + tid) + 1e-5f);
    scs[tid] = s;
    shs[tid] = __ldg(Bt + tid) - __ldg(Mn + tid) * s;
    sb1[tid] = __ldg(B1 + tid);
    b2s[tid] = __ldg(B2 + tid);
  }
  __syncthreads();

  int wid = tid >> 5;
  int wr = (wid & 3) * 32, wc = (wid >> 2) * 32;

  wmma::fragment<wmma::accumulator, 16, 16, 16, float> acc00, acc01, acc10,
      acc11;
  FILL_ACC32();
#pragma unroll
  for (int k = 0; k < 64; k += 16)
    MMA_STEP32(a_hi + wr * 72 + k, a_lo + wr * 72 + k, w1h + k * 72 + wc,
               w1l + k * 72 + wc);
  STORE_ACC32();
  __syncthreads();

  // t = relu(fs + agg'' + b1) -> a buffers (split)
  {
    int r = tid >> 1, c0 = (tid & 1) * 32;
    int grow = rb + r;
    const float* ag = (const float*)g_agg4f + (size_t)grow * 64 + c0;
#pragma unroll
    for (int q = 0; q < 8; q++) {
      int c = c0 + q * 4;
      float4 v = *(const float4*)(fs + r * 72 + c);
      float4 a = (grow < N) ? __ldg((const float4*)(ag + q * 4))
                            : make_float4(0.f, 0.f, 0.f, 0.f);
      float t0 = fmaxf(v.x + a.x + sb1[c + 0], 0.f);
      float t1 = fmaxf(v.y + a.y + sb1[c + 1], 0.f);
      float t2 = fmaxf(v.z + a.z + sb1[c + 2], 0.f);
      float t3 = fmaxf(v.w + a.w + sb1[c + 3], 0.f);
      __half h0, l0, h1, l1, h2, l2, h3, l3;
      split2(t0, h0, l0); split2(t1, h1, l1);
      split2(t2, h2, l2); split2(t3, h3, l3);
      *(__half2*)(a_hi + r * 72 + c) = __halves2half2(h0, h1);
      *(__half2*)(a_hi + r * 72 + c + 2) = __halves2half2(h2, h3);
      *(__half2*)(a_lo + r * 72 + c) = __halves2half2(l0, l1);
      *(__half2*)(a_lo + r * 72 + c + 2) = __halves2half2(l2, l3);
    }
  }
  __syncthreads();

  FILL_ACC32();
#pragma unroll
  for (int k = 0; k < 64; k += 16)
    MMA_STEP32(a_hi + wr * 72 + k, a_lo + wr * 72 + k, w2h + k * 72 + wc,
               w2l + k * 72 + wc);
  STORE_ACC32();
  __syncthreads();

  // h = relu(bn(fs + b2) + h_old);  h_old = hi+lo from global (exact)
  {
    int r = tid >> 1, c0 = (tid & 1) * 32;
    int grow = rb + r;
    if (grow < N) {
      const __half2* hh2 =
          (const __half2*)((const char*)g_hh4 + (size_t)grow * 128 + c0 * 2);
      const __half2* hl2 =
          (const __half2*)((const char*)g_hl4 + (size_t)grow * 128 + c0 * 2);
      __half2 oh[16], ol[16];
#pragma unroll
      for (int q = 0; q < 16; q++) {
        int c = c0 + 2 * q;
        float2 hi2 = __half22float2(hh2[q]);
        float2 lo2 = __half22float2(hl2[q]);
        float v0 = fs[r * 72 + c] + b2s[c];
        float v1 = fs[r * 72 + c + 1] + b2s[c + 1];
        float o0 = fmaxf(fmaf(v0, scs[c], shs[c]) + hi2.x + lo2.x, 0.f);
        float o1 =
            fmaxf(fmaf(v1, scs[c + 1], shs[c + 1]) + hi2.y + lo2.y, 0.f);
        __half h0, l0, h1, l1;
        split2(o0, h0, l0);
        split2(o1, h1, l1);
        oh[q] = __halves2half2(h0, h1);
        ol[q] = __halves2half2(l0, l1);
      }
      __half2* dh = (__half2*)((char*)g_hh4 + (size_t)grow * 128 + c0 * 2);
      __half2* dl = (__half2*)((char*)g_hl4 + (size_t)grow * 128 + c0 * 2);
#pragma unroll
      for (int q = 0; q < 16; q++) {
        dh[q] = oh[q];
        dl[q] = ol[q];
      }
    }
  }
}

// ---------------------------------------------------------------------------
// out = relu(h[:NQ] @ out_w1 + b1) @ out_w2 + b2   (warp per node)
// ---------------------------------------------------------------------------
__global__ void __launch_bounds__(256) out_kernel(
    const float* __restrict__ w1, const float* __restrict__ b1,
    const float* __restrict__ w2, const float* __restrict__ b2,
    float* __restrict__ out, int NQ) {
  int warp = (blockIdx.x * blockDim.x + threadIdx.x) >> 5;
  int lane = threadIdx.x & 31;
  if (warp >= NQ) return;
  float2 hh = __half22float2(((const __half2*)g_hh4)[(size_t)warp * 32 + lane]);
  float2 hl = __half22float2(((const __half2*)g_hl4)[(size_t)warp * 32 + lane]);
  float2 hv = make_float2(hh.x + hl.x, hh.y + hl.y);
  float acc = __ldg(b1 + lane);
#pragma unroll
  for (int kk = 0; kk < 32; kk++) {
    float hx = __shfl_sync(0xffffffffu, hv.x, kk);
    float hy = __shfl_sync(0xffffffffu, hv.y, kk);
    acc = fmaf(hx, __ldg(w1 + (2 * kk) * 32 + lane), acc);
    acc = fmaf(hy, __ldg(w1 + (2 * kk + 1) * 32 + lane), acc);
  }
  float v = fmaxf(acc, 0.f) * __ldg(w2 + lane);
#pragma unroll
  for (int o = 16; o; o >>= 1) v += __shfl_down_sync(0xffffffffu, v, o);
  if (lane == 0) out[warp] = v + __ldg(b2);
}

// ---------------------------------------------------------------------------
extern "C" void kernel_launch(void* const* d_in, const int* in_sizes, int n_in,
                              void* d_out, int out_size) {
  int off = (n_in >= 21) ? 1 : 0;
  const float* x      = (const float*)d_in[0];
  const int*   ei     = (const int*)d_in[1];
  const float* w_in   = (const float*)d_in[2 + off];
  const float* b_in   = (const float*)d_in[3 + off];
  const float* msg_w1 = (const float*)d_in[4 + off];
  const float* msg_b1 = (const float*)d_in[5 + off];
  const float* msg_w2 = (const float*)d_in[6 + off];
  const float* msg_b2 = (const float*)d_in[7 + off];
  const float* upd_w1 = (const float*)d_in[8 + off];
  const float* upd_b1 = (const float*)d_in[9 + off];
  const float* upd_w2 = (const float*)d_in[10 + off];
  const float* upd_b2 = (const float*)d_in[11 + off];
  const float* bn_g   = (const float*)d_in[12 + off];
  const float* bn_b   = (const float*)d_in[13 + off];
  const float* bn_m   = (const float*)d_in[14 + off];
  const float* bn_v   = (const float*)d_in[15 + off];
  const float* out_w1 = (const float*)d_in[16 + off];
  const float* out_b1 = (const float*)d_in[17 + off];
  const float* out_w2 = (const float*)d_in[18 + off];
  const float* out_b2 = (const float*)d_in[19 + off];

  int N = in_sizes[0] / 3;
  int E = in_sizes[1] / 2;
  int L = in_sizes[4 + off] / (64 * 64);
  int NQ = out_size;

  const int GEMM_SMEM =
      (2 * 128 * 72 + 4 * 64 * 72) * 2 + 128 * 72 * 4;  // 110,592 B
  cudaFuncSetAttribute(msg_kernel, cudaFuncAttributeMaxDynamicSharedMemorySize,
                       GEMM_SMEM);
  cudaFuncSetAttribute(upd_kernel, cudaFuncAttributeMaxDynamicSharedMemorySize,
                       GEMM_SMEM);

  int gb = (N + 127) / 128;
  int nb_scan = (N + 1023) / 1024;

  void* whp = nullptr;
  void* wlp = nullptr;
  void* cbp = nullptr;
  cudaGetSymbolAddress(&whp, g_wh4);
  cudaGetSymbolAddress(&wlp, g_wl4);
  cudaGetSymbolAddress(&cbp, g_cb);
  const __half* wh = (const __half*)whp;
  const __half* wl = (const __half*)wlp;
  const float* cb = (const float*)cbp;

  // Order: wsplit(1), wfuse(2), input(3), msg0(4) <- profiled slot, ...
  wprep_split_kernel<<<(L * 12288 + 255) / 256, 256>>>(msg_w1, upd_w1, upd_w2,
                                                       L);
  wprep_fuse_kernel<<<L, 256>>>(msg_w2, upd_w1, msg_b2);
  input_kernel<<<(N * 64 + 255) / 256, 256>>>(x, w_in, b_in, N);
  msg_kernel<<<gb, 256, GEMM_SMEM>>>(wh, wl, msg_b1, cb, N);
  zero_counts_kernel<<<(N + 255) / 256, 256>>>(N);
  hist_kernel<<<(E + 255) / 256, 256>>>(ei, E);
  scan1_kernel<<<nb_scan, 1024>>>(N);
  scan2_kernel<<<1, 128>>>(nb_scan);
  scan3_kernel<<<(N + 255) / 256, 256>>>(N);
  fill_kernel<<<(E + 255) / 256, 256>>>(ei, E);

  for (int l = 0; l < L; l++) {
    if (l > 0)
      msg_kernel<<<gb, 256, GEMM_SMEM>>>(wh + l * 16384, wl + l * 16384,
                                         msg_b1 + l * 64, cb + l * 64, N);
    gather_kernel<<<(N * 32 + 255) / 256, 256>>>(N);
    upd_kernel<<<gb, 256, GEMM_SMEM>>>(
        wh + l * 16384 + 8192, wl + l * 16384 + 8192, upd_b1 + l * 64,
        upd_b2 + l * 64, bn_g + l * 64, bn_b + l * 64, bn_m + l * 64,
        bn_v + l * 64, N);
  }

  out_kernel<<<(NQ * 32 + 255) / 256, 256>>>(out_w1, out_b1, out_w2, out_b2,
                                             (float*)d_out, NQ);
}

// round 12
// speedup vs baseline: 1.0446x; 1.0446x over previous
#include <cuda_runtime.h>
#include <cuda_fp16.h>
#include <mma.h>

using namespace nvcuda;

#define MAXN 100000
#define MAXE 1600000
#define MAXL 8

// Persistent scratch (no allocations allowed).
__device__ float4 g_hh4[MAXN * 8];     // h hi (half, N x 64)
__device__ float4 g_hl4[MAXN * 8];     // h lo
__device__ float4 g_Mh4[MAXN * 8];     // M'' (fp16, N x 64)
__device__ float4 g_agg4f[(MAXN + 128) * 16];  // agg'' (fp32, N x 64)
__device__ float4 g_wh4[MAXL * 2048];  // weights hi: 16384 half / layer
__device__ float4 g_wl4[MAXL * 2048];  // weights lo: 16384 half / layer
__device__ float g_cb[MAXL * 64];      // fused bias c = b2 @ updW1b
// CSR
__device__ int g_counts[MAXN];
__device__ int g_rowstart[MAXN];
__device__ int g_rowend[MAXN];
__device__ int g_csrsrc[MAXE];
__device__ int g_blocksum[128];

__device__ __forceinline__ void split2(float x, __half& hi, __half& lo) {
  hi = __float2half_rn(x);
  lo = __float2half_rn(x - __half2float(hi));
}

// ---------------------------------------------------------------------------
// wprep_split: copy+split msgW1 -> [0,4096), updW1a -> [8192,12288),
// updW2 -> [12288,16384). (V fills [4096,8192) in wprep_fuse.)
// ---------------------------------------------------------------------------
__global__ void __launch_bounds__(256) wprep_split_kernel(
    const float* __restrict__ mw1, const float* __restrict__ uw1,
    const float* __restrict__ uw2, int L) {
  int i = blockIdx.x * blockDim.x + threadIdx.x;
  if (i >= L * 12288) return;
  int l = i / 12288, off = i % 12288;
  int seg = off >> 12, r = off & 4095;
  float v;
  int dst;
  if (seg == 0) {
    v = __ldg(mw1 + l * 4096 + r);
    dst = l * 16384 + r;
  } else if (seg == 1) {
    v = __ldg(uw1 + l * 8192 + r);  // rows [0,64) = W1a
    dst = l * 16384 + 8192 + r;
  } else {
    v = __ldg(uw2 + l * 4096 + r);
    dst = l * 16384 + 12288 + r;
  }
  __half hi, lo;
  split2(v, hi, lo);
  ((__half*)g_wh4)[dst] = hi;
  ((__half*)g_wl4)[dst] = lo;
}

// ---------------------------------------------------------------------------
// wprep_fuse: V = msgW2 @ updW1b (64x64, fp32), c = msg_b2 @ updW1b.
// One block per layer.
// ---------------------------------------------------------------------------
__global__ void __launch_bounds__(256) wprep_fuse_kernel(
    const float* __restrict__ mw2, const float* __restrict__ uw1,
    const float* __restrict__ mb2) {
  __shared__ float su[4096];  // updW1b (rows [64,128) of uw1)
  __shared__ float sw[4096];  // msgW2
  int l = blockIdx.x, t = threadIdx.x;
  for (int i = t; i < 4096; i += 256) {
    su[i] = __ldg(uw1 + l * 8192 + 4096 + i);
    sw[i] = __ldg(mw2 + l * 4096 + i);
  }
  __syncthreads();
  for (int e = t; e < 4096; e += 256) {
    int k = e >> 6, n = e & 63;
    float s = 0.f;
#pragma unroll 8
    for (int j = 0; j < 64; j++) s += sw[k * 64 + j] * su[j * 64 + n];
    __half hi, lo;
    split2(s, hi, lo);
    ((__half*)g_wh4)[l * 16384 + 4096 + e] = hi;
    ((__half*)g_wl4)[l * 16384 + 4096 + e] = lo;
  }
  if (t < 64) {
    float s = 0.f;
#pragma unroll 8
    for (int j = 0; j < 64; j++) s += __ldg(mb2 + l * 64 + j) * su[j * 64 + t];
    g_cb[l * 64 + t] = s;
  }
}

// ---------------------------------------------------------------------------
// h = relu(x @ w_in + b_in), stored split
// ---------------------------------------------------------------------------
__global__ void __launch_bounds__(256) input_kernel(
    const float* __restrict__ x, const float* __restrict__ w_in,
    const float* __restrict__ b_in, int N) {
  int i = blockIdx.x * blockDim.x + threadIdx.x;
  if (i >= N * 64) return;
  int node = i >> 6, c = i & 63;
  float acc = __ldg(b_in + c);
  acc = fmaf(__ldg(x + node * 3 + 0), __ldg(w_in + c), acc);
  acc = fmaf(__ldg(x + node * 3 + 1), __ldg(w_in + 64 + c), acc);
  acc = fmaf(__ldg(x + node * 3 + 2), __ldg(w_in + 128 + c), acc);
  float h = fmaxf(acc, 0.f);
  __half hi, lo;
  split2(h, hi, lo);
  ((__half*)g_hh4)[i] = hi;
  ((__half*)g_hl4)[i] = lo;
}

// ---------------------------------------------------------------------------
// CSR build
// ---------------------------------------------------------------------------
__global__ void __launch_bounds__(256) zero_counts_kernel(int N) {
  int i = blockIdx.x * blockDim.x + threadIdx.x;
  if (i < N) g_counts[i] = 0;
}

__global__ void __launch_bounds__(256) hist_kernel(const int* __restrict__ ei,
                                                   int E) {
  int e = blockIdx.x * blockDim.x + threadIdx.x;
  if (e < E) atomicAdd(&g_counts[__ldg(ei + E + e)], 1);
}

__global__ void __launch_bounds__(1024) scan1_kernel(int N) {
  __shared__ int sh[1024];
  int t = threadIdx.x;
  int idx = blockIdx.x * 1024 + t;
  int v = (idx < N) ? g_counts[idx] : 0;
  sh[t] = v;
  __syncthreads();
#pragma unroll
  for (int off = 1; off < 1024; off <<= 1) {
    int x = (t >= off) ? sh[t - off] : 0;
    __syncthreads();
    sh[t] += x;
    __syncthreads();
  }
  if (idx < N) g_rowstart[idx] = sh[t] - v;
  if (t == 1023) g_blocksum[blockIdx.x] = sh[1023];
}

__global__ void __launch_bounds__(128) scan2_kernel(int nb) {
  __shared__ int sh[128];
  int t = threadIdx.x;
  int v = (t < nb) ? g_blocksum[t] : 0;
  sh[t] = v;
  __syncthreads();
#pragma unroll
  for (int off = 1; off < 128; off <<= 1) {
    int x = (t >= off) ? sh[t - off] : 0;
    __syncthreads();
    sh[t] += x;
    __syncthreads();
  }
  if (t < nb) g_blocksum[t] = sh[t] - v;
}

__global__ void __launch_bounds__(256) scan3_kernel(int N) {
  int i = blockIdx.x * blockDim.x + threadIdx.x;
  if (i < N) {
    int v = g_rowstart[i] + g_blocksum[i >> 10];
    g_rowstart[i] = v;
    g_rowend[i] = v;
  }
}

__global__ void __launch_bounds__(256) fill_kernel(const int* __restrict__ ei,
                                                   int E) {
  int e = blockIdx.x * blockDim.x + threadIdx.x;
  if (e < E) {
    int d = __ldg(ei + E + e);
    int pos = atomicAdd(&g_rowend[d], 1);
    g_csrsrc[pos] = __ldg(ei + e);
  }
}

// ---------------------------------------------------------------------------
// agg''[i] = sum_{e: dst(e)=i} M''[src(e)]   (warp per node, vectorized)
// Lane layout: sub = lane>>3 (edge slot, 4 concurrent edges), ch = lane&7
// (16B chunk of the 128B M row). Each lane: LDG.128 per edge -> 8 halves ->
// 8 fp32 accumulators. Final: shfl_xor reduce over sub, lanes 0..7 store.
// ---------------------------------------------------------------------------
__global__ void __launch_bounds__(256) gather_kernel(int N) {
  int w = (blockIdx.x * blockDim.x + threadIdx.x) >> 5;
  int lane = threadIdx.x & 31;
  if (w >= N) return;
  int s = __ldg(&g_rowstart[w]);
  int e = __ldg(&g_rowend[w]);
  int sub = lane >> 3, ch = lane & 7;

  float acc[8];
#pragma unroll
  for (int i = 0; i < 8; i++) acc[i] = 0.f;

  for (int j = s + sub; j < e; j += 4) {
    int src = __ldg(&g_csrsrc[j]);
    uint4 v = __ldg((const uint4*)((const char*)g_Mh4 + (size_t)src * 128) +
                    ch);
    const __half2* hp = (const __half2*)&v;
#pragma unroll
    for (int q = 0; q < 4; q++) {
      float2 f = __half22float2(hp[q]);
      acc[2 * q + 0] += f.x;
      acc[2 * q + 1] += f.y;
    }
  }
  // reduce the 4 edge slots (lanes differing in bits 3..4)
#pragma unroll
  for (int i = 0; i < 8; i++) {
    acc[i] += __shfl_xor_sync(0xffffffffu, acc[i], 8);
    acc[i] += __shfl_xor_sync(0xffffffffu, acc[i], 16);
  }
  if (lane < 8) {
    float* ag = (float*)g_agg4f + (size_t)w * 64 + lane * 8;
    ((float4*)ag)[0] = make_float4(acc[0], acc[1], acc[2], acc[3]);
    ((float4*)ag)[1] = make_float4(acc[4], acc[5], acc[6], acc[7]);
  }
}

// 3-term split MMA, 32x32 warp tile (2x2 16x16 frags), one 16-k chunk.
#define MMA_STEP32(APH, APL, BPH, BPL)                                       \
  {                                                                          \
    wmma::fragment<wmma::matrix_a, 16, 16, 16, __half, wmma::row_major>    \
        ah0, ah1, al0, al1;                                                  \
    wmma::fragment<wmma::matrix_b, 16, 16, 16, __half, wmma::row_major>    \
        bh0, bh1, bl0, bl1;                                                  \
    wmma::load_matrix_sync(ah0, (APH), 72);                                  \
    wmma::load_matrix_sync(ah1, (APH) + 16 * 72, 72);                        \
    wmma::load_matrix_sync(al0, (APL), 72);                                  \
    wmma::load_matrix_sync(al1, (APL) + 16 * 72, 72);                        \
    wmma::load_matrix_sync(bh0, (BPH), 72);                                  \
    wmma::load_matrix_sync(bh1, (BPH) + 16, 72);                             \
    wmma::load_matrix_sync(bl0, (BPL), 72);                                  \
    wmma::load_matrix_sync(bl1, (BPL) + 16, 72);                             \
    wmma::mma_sync(acc00, ah0, bh0, acc00);                                  \
    wmma::mma_sync(acc00, al0, bh0, acc00);                                  \
    wmma::mma_sync(acc00, ah0, bl0, acc00);                                  \
    wmma::mma_sync(acc01, ah0, bh1, acc01);                                  \
    wmma::mma_sync(acc01, al0, bh1, acc01);                                  \
    wmma::mma_sync(acc01, ah0, bl1, acc01);                                  \
    wmma::mma_sync(acc10, ah1, bh0, acc10);                                  \
    wmma::mma_sync(acc10, al1, bh0, acc10);                                  \
    wmma::mma_sync(acc10, ah1, bl0, acc10);                                  \
    wmma::mma_sync(acc11, ah1, bh1, acc11);                                  \
    wmma::mma_sync(acc11, al1, bh1, acc11);                                  \
    wmma::mma_sync(acc11, ah1, bl1, acc11);                                  \
  }

#define STORE_ACC32()                                                        \
  {                                                                          \
    wmma::store_matrix_sync(fs + wr * 72 + wc, acc00, 72,                    \
                            wmma::mem_row_major);                            \
    wmma::store_matrix_sync(fs + wr * 72 + wc + 16, acc01, 72,               \
                            wmma::mem_row_major);                            \
    wmma::store_matrix_sync(fs + (wr + 16) * 72 + wc, acc10, 72,             \
                            wmma::mem_row_major);                            \
    wmma::store_matrix_sync(fs + (wr + 16) * 72 + wc + 16, acc11, 72,        \
                            wmma::mem_row_major);                            \
  }

#define FILL_ACC32()                                                         \
  {                                                                          \
    wmma::fill_fragment(acc00, 0.f);                                         \
    wmma::fill_fragment(acc01, 0.f);                                         \
    wmma::fill_fragment(acc10, 0.f);                                         \
    wmma::fill_fragment(acc11, 0.f);                                         \
  }

// Common staging: W1 (wh+0), W2 (wh+4096), A = split h. 128-row tile.
#define STAGE_COMMON()                                                       \
  for (int j = tid; j < 512; j += 256) {                                     \
    int k = j >> 3, ch = j & 7;                                              \
    *(uint4*)((char*)w1h + k * 144 + ch * 16) = __ldg((const uint4*)wh + j); \
    *(uint4*)((char*)w1l + k * 144 + ch * 16) = __ldg((const uint4*)wl + j); \
    *(uint4*)((char*)w2h + k * 144 + ch * 16) =                              \
        __ldg((const uint4*)(wh + 4096) + j);                                \
    *(uint4*)((char*)w2l + k * 144 + ch * 16) =                              \
        __ldg((const uint4*)(wl + 4096) + j);                                \
  }                                                                          \
  for (int j = tid; j < 1024; j += 256) {                                    \
    int r = j >> 3, ch = j & 7;                                              \
    int grow = rb + r;                                                       \
    uint4 vh = make_uint4(0, 0, 0, 0), vl = make_uint4(0, 0, 0, 0);          \
    if (grow < N) {                                                          \
      vh = __ldg((const uint4*)((const char*)g_hh4 + (size_t)grow * 128) +   \
                 ch);                                                        \
      vl = __ldg((const uint4*)((const char*)g_hl4 + (size_t)grow * 128) +   \
                 ch);                                                        \
    }                                                                        \
    *(uint4*)((char*)a_hi + r * 144 + ch * 16) = vh;                         \
    *(uint4*)((char*)a_lo + r * 144 + ch * 16) = vl;                         \
  }

// ---------------------------------------------------------------------------
// msg: M'' = relu(h @ W1 + b1) @ V + c.   128-row tile, 4 barriers.
// ---------------------------------------------------------------------------
__global__ void __launch_bounds__(256) msg_kernel(
    const __half* __restrict__ wh, const __half* __restrict__ wl,
    const float* __restrict__ B1, const float* __restrict__ CB, int N) {
  extern __shared__ char smc[];
  __half* a_hi = (__half*)smc;       // 128 x 72
  __half* a_lo = a_hi + 128 * 72;
  __half* w1h = a_lo + 128 * 72;     // 64 x 72
  __half* w1l = w1h + 64 * 72;
  __half* w2h = w1l + 64 * 72;       // V
  __half* w2l = w2h + 64 * 72;
  float* fs = (float*)(w2l + 64 * 72);  // 128 x 72
  __shared__ float sb1[64], sb2[64];

  int tid = threadIdx.x;
  int rb = blockIdx.x * 128;

  STAGE_COMMON();
  if (tid < 64) {
    sb1[tid] = __ldg(B1 + tid);
    sb2[tid] = __ldg(CB + tid);
  }
  __syncthreads();

  int wid = tid >> 5;
  int wr = (wid & 3) * 32, wc = (wid >> 2) * 32;

  wmma::fragment<wmma::accumulator, 16, 16, 16, float> acc00, acc01, acc10,
      acc11;
  FILL_ACC32();
#pragma unroll
  for (int k = 0; k < 64; k += 16)
    MMA_STEP32(a_hi + wr * 72 + k, a_lo + wr * 72 + k, w1h + k * 72 + wc,
               w1l + k * 72 + wc);
  STORE_ACC32();
  __syncthreads();

  // t = relu(fs + b1) -> a buffers (split)
  {
    int r = tid >> 1, c0 = (tid & 1) * 32;
#pragma unroll
    for (int q = 0; q < 8; q++) {
      int c = c0 + q * 4;
      float4 v = *(const float4*)(fs + r * 72 + c);
      float t0 = fmaxf(v.x + sb1[c + 0], 0.f);
      float t1 = fmaxf(v.y + sb1[c + 1], 0.f);
      float t2 = fmaxf(v.z + sb1[c + 2], 0.f);
      float t3 = fmaxf(v.w + sb1[c + 3], 0.f);
      __half h0, l0, h1, l1, h2, l2, h3, l3;
      split2(t0, h0, l0); split2(t1, h1, l1);
      split2(t2, h2, l2); split2(t3, h3, l3);
      *(__half2*)(a_hi + r * 72 + c) = __halves2half2(h0, h1);
      *(__half2*)(a_hi + r * 72 + c + 2) = __halves2half2(h2, h3);
      *(__half2*)(a_lo + r * 72 + c) = __halves2half2(l0, l1);
      *(__half2*)(a_lo + r * 72 + c + 2) = __halves2half2(l2, l3);
    }
  }
  __syncthreads();

  FILL_ACC32();
#pragma unroll
  for (int k = 0; k < 64; k += 16)
    MMA_STEP32(a_hi + wr * 72 + k, a_lo + wr * 72 + k, w2h + k * 72 + wc,
               w2l + k * 72 + wc);
  STORE_ACC32();
  __syncthreads();

  // M'' = fs + c  (fp16, straight to global)
  {
    int r = tid >> 1, c0 = (tid & 1) * 32;
    int grow = rb + r;
    if (grow < N) {
      __half* mp = (__half*)g_Mh4 + (size_t)grow * 64 + c0;
#pragma unroll
      for (int q = 0; q < 8; q++) {
        int c = c0 + q * 4;
        float4 v = *(const float4*)(fs + r * 72 + c);
        *(__half2*)(mp + q * 4) =
            __floats2half2_rn(v.x + sb2[c + 0], v.y + sb2[c + 1]);
        *(__half2*)(mp + q * 4 + 2) =
            __floats2half2_rn(v.z + sb2[c + 2], v.w + sb2[c + 3]);
      }
    }
  }
}

// ---------------------------------------------------------------------------
// upd: t = relu(h @ W1a + agg'' + b1); hn = t @ W2 + b2; bn; h = relu(hn+h)
// 128-row tile, identical shape to msg. agg'' read fp32 from global;
// residual h_old read fp32-exact (hi+lo) from global at epilogue.
// ---------------------------------------------------------------------------
__global__ void __launch_bounds__(256) upd_kernel(
    const __half* __restrict__ wh, const __half* __restrict__ wl,
    const float* __restrict__ B1, const float* __restrict__ B2,
    const float* __restrict__ Gm, const float* __restrict__ Bt,
    const float* __restrict__ Mn, const float* __restrict__ Vr, int N) {
  extern __shared__ char smc[];
  __half* a_hi = (__half*)smc;       // 128 x 72
  __half* a_lo = a_hi + 128 * 72;
  __half* w1h = a_lo + 128 * 72;     // W1a 64 x 72
  __half* w1l = w1h + 64 * 72;
  __half* w2h = w1l + 64 * 72;       // W2 64 x 72
  __half* w2l = w2h + 64 * 72;
  float* fs = (float*)(w2l + 64 * 72);  // 128 x 72
  __shared__ float sb1[64], b2s[64], scs[64], shs[64];

  int tid = threadIdx.x;
  int rb = blockIdx.x * 128;

  STAGE_COMMON();
  if (tid < 64) {
    float s = __ldg(Gm + tid) * rsqrtf(__ldg(Vr + tid) + 1e-5f);
    scs[tid] = s;
    shs[tid] = __ldg(Bt + tid) - __ldg(Mn + tid) * s;
    sb1[tid] = __ldg(B1 + tid);
    b2s[tid] = __ldg(B2 + tid);
  }
  __syncthreads();

  int wid = tid >> 5;
  int wr = (wid & 3) * 32, wc = (wid >> 2) * 32;

  wmma::fragment<wmma::accumulator, 16, 16, 16, float> acc00, acc01, acc10,
      acc11;
  FILL_ACC32();
#pragma unroll
  for (int k = 0; k < 64; k += 16)
    MMA_STEP32(a_hi + wr * 72 + k, a_lo + wr * 72 + k, w1h + k * 72 + wc,
               w1l + k * 72 + wc);
  STORE_ACC32();
  __syncthreads();

  // t = relu(fs + agg'' + b1) -> a buffers (split)
  {
    int r = tid >> 1, c0 = (tid & 1) * 32;
    int grow = rb + r;
    const float* ag = (const float*)g_agg4f + (size_t)grow * 64 + c0;
#pragma unroll
    for (int q = 0; q < 8; q++) {
      int c = c0 + q * 4;
      float4 v = *(const float4*)(fs + r * 72 + c);
      float4 a = (grow < N) ? __ldg((const float4*)(ag + q * 4))
                            : make_float4(0.f, 0.f, 0.f, 0.f);
      float t0 = fmaxf(v.x + a.x + sb1[c + 0], 0.f);
      float t1 = fmaxf(v.y + a.y + sb1[c + 1], 0.f);
      float t2 = fmaxf(v.z + a.z + sb1[c + 2], 0.f);
      float t3 = fmaxf(v.w + a.w + sb1[c + 3], 0.f);
      __half h0, l0, h1, l1, h2, l2, h3, l3;
      split2(t0, h0, l0); split2(t1, h1, l1);
      split2(t2, h2, l2); split2(t3, h3, l3);
      *(__half2*)(a_hi + r * 72 + c) = __halves2half2(h0, h1);
      *(__half2*)(a_hi + r * 72 + c + 2) = __halves2half2(h2, h3);
      *(__half2*)(a_lo + r * 72 + c) = __halves2half2(l0, l1);
      *(__half2*)(a_lo + r * 72 + c + 2) = __halves2half2(l2, l3);
    }
  }
  __syncthreads();

  FILL_ACC32();
#pragma unroll
  for (int k = 0; k < 64; k += 16)
    MMA_STEP32(a_hi + wr * 72 + k, a_lo + wr * 72 + k, w2h + k * 72 + wc,
               w2l + k * 72 + wc);
  STORE_ACC32();
  __syncthreads();

  // h = relu(bn(fs + b2) + h_old);  h_old = hi+lo from global (exact)
  {
    int r = tid >> 1, c0 = (tid & 1) * 32;
    int grow = rb + r;
    if (grow < N) {
      const __half2* hh2 =
          (const __half2*)((const char*)g_hh4 + (size_t)grow * 128 + c0 * 2);
      const __half2* hl2 =
          (const __half2*)((const char*)g_hl4 + (size_t)grow * 128 + c0 * 2);
      __half2 oh[16], ol[16];
#pragma unroll
      for (int q = 0; q < 16; q++) {
        int c = c0 + 2 * q;
        float2 hi2 = __half22float2(hh2[q]);
        float2 lo2 = __half22float2(hl2[q]);
        float v0 = fs[r * 72 + c] + b2s[c];
        float v1 = fs[r * 72 + c + 1] + b2s[c + 1];
        float o0 = fmaxf(fmaf(v0, scs[c], shs[c]) + hi2.x + lo2.x, 0.f);
        float o1 =
            fmaxf(fmaf(v1, scs[c + 1], shs[c + 1]) + hi2.y + lo2.y, 0.f);
        __half h0, l0, h1, l1;
        split2(o0, h0, l0);
        split2(o1, h1, l1);
        oh[q] = __halves2half2(h0, h1);
        ol[q] = __halves2half2(l0, l1);
      }
      __half2* dh = (__half2*)((char*)g_hh4 + (size_t)grow * 128 + c0 * 2);
      __half2* dl = (__half2*)((char*)g_hl4 + (size_t)grow * 128 + c0 * 2);
#pragma unroll
      for (int q = 0; q < 16; q++) {
        dh[q] = oh[q];
        dl[q] = ol[q];
      }
    }
  }
}

// ---------------------------------------------------------------------------
// out = relu(h[:NQ] @ out_w1 + b1) @ out_w2 + b2   (warp per node)
// ---------------------------------------------------------------------------
__global__ void __launch_bounds__(256) out_kernel(
    const float* __restrict__ w1, const float* __restrict__ b1,
    const float* __restrict__ w2, const float* __restrict__ b2,
    float* __restrict__ out, int NQ) {
  int warp = (blockIdx.x * blockDim.x + threadIdx.x) >> 5;
  int lane = threadIdx.x & 31;
  if (warp >= NQ) return;
  float2 hh = __half22float2(((const __half2*)g_hh4)[(size_t)warp * 32 + lane]);
  float2 hl = __half22float2(((const __half2*)g_hl4)[(size_t)warp * 32 + lane]);
  float2 hv = make_float2(hh.x + hl.x, hh.y + hl.y);
  float acc = __ldg(b1 + lane);
#pragma unroll
  for (int kk = 0; kk < 32; kk++) {
    float hx = __shfl_sync(0xffffffffu, hv.x, kk);
    float hy = __shfl_sync(0xffffffffu, hv.y, kk);
    acc = fmaf(hx, __ldg(w1 + (2 * kk) * 32 + lane), acc);
    acc = fmaf(hy, __ldg(w1 + (2 * kk + 1) * 32 + lane), acc);
  }
  float v = fmaxf(acc, 0.f) * __ldg(w2 + lane);
#pragma unroll
  for (int o = 16; o; o >>= 1) v += __shfl_down_sync(0xffffffffu, v, o);
  if (lane == 0) out[warp] = v + __ldg(b2);
}

// ---------------------------------------------------------------------------
extern "C" void kernel_launch(void* const* d_in, const int* in_sizes, int n_in,
                              void* d_out, int out_size) {
  int off = (n_in >= 21) ? 1 : 0;
  const float* x      = (const float*)d_in[0];
  const int*   ei     = (const int*)d_in[1];
  const float* w_in   = (const float*)d_in[2 + off];
  const float* b_in   = (const float*)d_in[3 + off];
  const float* msg_w1 = (const float*)d_in[4 + off];
  const float* msg_b1 = (const float*)d_in[5 + off];
  const float* msg_w2 = (const float*)d_in[6 + off];
  const float* msg_b2 = (const float*)d_in[7 + off];
  const float* upd_w1 = (const float*)d_in[8 + off];
  const float* upd_b1 = (const float*)d_in[9 + off];
  const float* upd_w2 = (const float*)d_in[10 + off];
  const float* upd_b2 = (const float*)d_in[11 + off];
  const float* bn_g   = (const float*)d_in[12 + off];
  const float* bn_b   = (const float*)d_in[13 + off];
  const float* bn_m   = (const float*)d_in[14 + off];
  const float* bn_v   = (const float*)d_in[15 + off];
  const float* out_w1 = (const float*)d_in[16 + off];
  const float* out_b1 = (const float*)d_in[17 + off];
  const float* out_w2 = (const float*)d_in[18 + off];
  const float* out_b2 = (const float*)d_in[19 + off];

  int N = in_sizes[0] / 3;
  int E = in_sizes[1] / 2;
  int L = in_sizes[4 + off] / (64 * 64);
  int NQ = out_size;

  const int GEMM_SMEM =
      (2 * 128 * 72 + 4 * 64 * 72) * 2 + 128 * 72 * 4;  // 110,592 B
  cudaFuncSetAttribute(msg_kernel, cudaFuncAttributeMaxDynamicSharedMemorySize,
                       GEMM_SMEM);
  cudaFuncSetAttribute(upd_kernel, cudaFuncAttributeMaxDynamicSharedMemorySize,
                       GEMM_SMEM);

  int gb = (N + 127) / 128;
  int nb_scan = (N + 1023) / 1024;

  void* whp = nullptr;
  void* wlp = nullptr;
  void* cbp = nullptr;
  cudaGetSymbolAddress(&whp, g_wh4);
  cudaGetSymbolAddress(&wlp, g_wl4);
  cudaGetSymbolAddress(&cbp, g_cb);
  const __half* wh = (const __half*)whp;
  const __half* wl = (const __half*)wlp;
  const float* cb = (const float*)cbp;

  // Order: wsplit(1), wfuse(2), input(3), msg0(4) <- profiled slot, ...
  wprep_split_kernel<<<(L * 12288 + 255) / 256, 256>>>(msg_w1, upd_w1, upd_w2,
                                                       L);
  wprep_fuse_kernel<<<L, 256>>>(msg_w2, upd_w1, msg_b2);
  input_kernel<<<(N * 64 + 255) / 256, 256>>>(x, w_in, b_in, N);
  msg_kernel<<<gb, 256, GEMM_SMEM>>>(wh, wl, msg_b1, cb, N);
  zero_counts_kernel<<<(N + 255) / 256, 256>>>(N);
  hist_kernel<<<(E + 255) / 256, 256>>>(ei, E);
  scan1_kernel<<<nb_scan, 1024>>>(N);
  scan2_kernel<<<1, 128>>>(nb_scan);
  scan3_kernel<<<(N + 255) / 256, 256>>>(N);
  fill_kernel<<<(E + 255) / 256, 256>>>(ei, E);

  for (int l = 0; l < L; l++) {
    if (l > 0)
      msg_kernel<<<gb, 256, GEMM_SMEM>>>(wh + l * 16384, wl + l * 16384,
                                         msg_b1 + l * 64, cb + l * 64, N);
    gather_kernel<<<(N * 32 + 255) / 256, 256>>>(N);
    upd_kernel<<<gb, 256, GEMM_SMEM>>>(
        wh + l * 16384 + 8192, wl + l * 16384 + 8192, upd_b1 + l * 64,
        upd_b2 + l * 64, bn_g + l * 64, bn_b + l * 64, bn_m + l * 64,
        bn_v + l * 64, N);
  }

  out_kernel<<<(NQ * 32 + 255) / 256, 256>>>(out_w1, out_b1, out_w2, out_b2,
                                             (float*)d_out, NQ);
}

// round 14
// speedup vs baseline: 1.1431x; 1.0942x over previous
#include <cuda_runtime.h>
#include <cuda_fp16.h>
#include <cstdint>

#define MAXN 100000
#define MAXE 1600000
#define MAXL 8

// Persistent scratch (no allocations allowed).
__device__ float4 g_hh4[MAXN * 8];     // h hi (half, N x 64)
__device__ float4 g_hl4[MAXN * 8];     // h lo
__device__ float4 g_Mh4[MAXN * 8];     // M'' (fp16, N x 64)
__device__ float4 g_agg4f[(MAXN + 128) * 16];  // agg'' (fp32, N x 64)
__device__ float4 g_wh4[MAXL * 2048];  // weights hi: 16384 half / layer
__device__ float4 g_wl4[MAXL * 2048];  // weights lo: 16384 half / layer
__device__ float g_cb[MAXL * 64];      // fused bias c = b2 @ updW1b
// CSR
__device__ int g_counts[MAXN];
__device__ int g_rowstart[MAXN];
__device__ int g_rowend[MAXN];
__device__ int g_csrsrc[MAXE];
__device__ int g_blocksum[128];

__device__ __forceinline__ void split2(float x, __half& hi, __half& lo) {
  hi = __float2half_rn(x);
  lo = __float2half_rn(x - __half2float(hi));
}

__device__ __forceinline__ void splitpack2(float x, float y, uint32_t& hi,
                                           uint32_t& lo) {
  __half hx, lx, hy, ly;
  split2(x, hx, lx);
  split2(y, hy, ly);
  __half2 ph = __halves2half2(hx, hy), pl = __halves2half2(lx, ly);
  hi = *(uint32_t*)&ph;
  lo = *(uint32_t*)&pl;
}

__device__ __forceinline__ uint32_t sm32(const void* p) {
  return (uint32_t)__cvta_generic_to_shared(p);
}
__device__ __forceinline__ void ldsm4(const void* p, uint32_t* r) {
  asm volatile(
      "ldmatrix.sync.aligned.m8n8.x4.shared.b16 {%0,%1,%2,%3}, [%4];"
      : "=r"(r[0]), "=r"(r[1]), "=r"(r[2]), "=r"(r[3])
      : "r"(sm32(p)));
}
__device__ __forceinline__ void ldsm4t(const void* p, uint32_t* r) {
  asm volatile(
      "ldmatrix.sync.aligned.m8n8.x4.trans.shared.b16 {%0,%1,%2,%3}, [%4];"
      : "=r"(r[0]), "=r"(r[1]), "=r"(r[2]), "=r"(r[3])
      : "r"(sm32(p)));
}
__device__ __forceinline__ void mma16816(float* c, const uint32_t* a,
                                         const uint32_t* b) {
  asm volatile(
      "mma.sync.aligned.m16n8k16.row.col.f32.f16.f16.f32 "
      "{%0,%1,%2,%3}, {%4,%5,%6,%7}, {%8,%9}, {%0,%1,%2,%3};"
      : "+f"(c[0]), "+f"(c[1]), "+f"(c[2]), "+f"(c[3])
      : "r"(a[0]), "r"(a[1]), "r"(a[2]), "r"(a[3]), "r"(b[0]), "r"(b[1]));
}

// ---------------------------------------------------------------------------
// wprep_split: copy+split msgW1 -> [0,4096), updW1a -> [8192,12288),
// updW2 -> [12288,16384). (V fills [4096,8192) in wprep_fuse.)
// ---------------------------------------------------------------------------
__global__ void __launch_bounds__(256) wprep_split_kernel(
    const float* __restrict__ mw1, const float* __restrict__ uw1,
    const float* __restrict__ uw2, int L) {
  int i = blockIdx.x * blockDim.x + threadIdx.x;
  if (i >= L * 12288) return;
  int l = i / 12288, off = i % 12288;
  int seg = off >> 12, r = off & 4095;
  float v;
  int dst;
  if (seg == 0) {
    v = __ldg(mw1 + l * 4096 + r);
    dst = l * 16384 + r;
  } else if (seg == 1) {
    v = __ldg(uw1 + l * 8192 + r);  // rows [0,64) = W1a
    dst = l * 16384 + 8192 + r;
  } else {
    v = __ldg(uw2 + l * 4096 + r);
    dst = l * 16384 + 12288 + r;
  }
  __half hi, lo;
  split2(v, hi, lo);
  ((__half*)g_wh4)[dst] = hi;
  ((__half*)g_wl4)[dst] = lo;
}

// ---------------------------------------------------------------------------
// wprep_fuse: V = msgW2 @ updW1b (64x64, fp32), c = msg_b2 @ updW1b.
// ---------------------------------------------------------------------------
__global__ void __launch_bounds__(256) wprep_fuse_kernel(
    const float* __restrict__ mw2, const float* __restrict__ uw1,
    const float* __restrict__ mb2) {
  __shared__ float su[4096];  // updW1b (rows [64,128) of uw1)
  __shared__ float sw[4096];  // msgW2
  int l = blockIdx.x, t = threadIdx.x;
  for (int i = t; i < 4096; i += 256) {
    su[i] = __ldg(uw1 + l * 8192 + 4096 + i);
    sw[i] = __ldg(mw2 + l * 4096 + i);
  }
  __syncthreads();
  for (int e = t; e < 4096; e += 256) {
    int k = e >> 6, n = e & 63;
    float s = 0.f;
#pragma unroll 8
    for (int j = 0; j < 64; j++) s += sw[k * 64 + j] * su[j * 64 + n];
    __half hi, lo;
    split2(s, hi, lo);
    ((__half*)g_wh4)[l * 16384 + 4096 + e] = hi;
    ((__half*)g_wl4)[l * 16384 + 4096 + e] = lo;
  }
  if (t < 64) {
    float s = 0.f;
#pragma unroll 8
    for (int j = 0; j < 64; j++) s += __ldg(mb2 + l * 64 + j) * su[j * 64 + t];
    g_cb[l * 64 + t] = s;
  }
}

// ---------------------------------------------------------------------------
// h = relu(x @ w_in + b_in), stored split
// ---------------------------------------------------------------------------
__global__ void __launch_bounds__(256) input_kernel(
    const float* __restrict__ x, const float* __restrict__ w_in,
    const float* __restrict__ b_in, int N) {
  int i = blockIdx.x * blockDim.x + threadIdx.x;
  if (i >= N * 64) return;
  int node = i >> 6, c = i & 63;
  float acc = __ldg(b_in + c);
  acc = fmaf(__ldg(x + node * 3 + 0), __ldg(w_in + c), acc);
  acc = fmaf(__ldg(x + node * 3 + 1), __ldg(w_in + 64 + c), acc);
  acc = fmaf(__ldg(x + node * 3 + 2), __ldg(w_in + 128 + c), acc);
  float h = fmaxf(acc, 0.f);
  __half hi, lo;
  split2(h, hi, lo);
  ((__half*)g_hh4)[i] = hi;
  ((__half*)g_hl4)[i] = lo;
}

// ---------------------------------------------------------------------------
// CSR build
// ---------------------------------------------------------------------------
__global__ void __launch_bounds__(256) zero_counts_kernel(int N) {
  int i = blockIdx.x * blockDim.x + threadIdx.x;
  if (i < N) g_counts[i] = 0;
}

__global__ void __launch_bounds__(256) hist_kernel(const int* __restrict__ ei,
                                                   int E) {
  int e = blockIdx.x * blockDim.x + threadIdx.x;
  if (e < E) atomicAdd(&g_counts[__ldg(ei + E + e)], 1);
}

__global__ void __launch_bounds__(1024) scan1_kernel(int N) {
  __shared__ int sh[1024];
  int t = threadIdx.x;
  int idx = blockIdx.x * 1024 + t;
  int v = (idx < N) ? g_counts[idx] : 0;
  sh[t] = v;
  __syncthreads();
#pragma unroll
  for (int off = 1; off < 1024; off <<= 1) {
    int x = (t >= off) ? sh[t - off] : 0;
    __syncthreads();
    sh[t] += x;
    __syncthreads();
  }
  if (idx < N) g_rowstart[idx] = sh[t] - v;
  if (t == 1023) g_blocksum[blockIdx.x] = sh[1023];
}

__global__ void __launch_bounds__(128) scan2_kernel(int nb) {
  __shared__ int sh[128];
  int t = threadIdx.x;
  int v = (t < nb) ? g_blocksum[t] : 0;
  sh[t] = v;
  __syncthreads();
#pragma unroll
  for (int off = 1; off < 128; off <<= 1) {
    int x = (t >= off) ? sh[t - off] : 0;
    __syncthreads();
    sh[t] += x;
    __syncthreads();
  }
  if (t < nb) g_blocksum[t] = sh[t] - v;
}

__global__ void __launch_bounds__(256) scan3_kernel(int N) {
  int i = blockIdx.x * blockDim.x + threadIdx.x;
  if (i < N) {
    int v = g_rowstart[i] + g_blocksum[i >> 10];
    g_rowstart[i] = v;
    g_rowend[i] = v;
  }
}

__global__ void __launch_bounds__(256) fill_kernel(const int* __restrict__ ei,
                                                   int E) {
  int e = blockIdx.x * blockDim.x + threadIdx.x;
  if (e < E) {
    int d = __ldg(ei + E + e);
    int pos = atomicAdd(&g_rowend[d], 1);
    g_csrsrc[pos] = __ldg(ei + e);
  }
}

// ---------------------------------------------------------------------------
// agg''[i] = sum_{e: dst(e)=i} M''[src(e)]   (warp per node, vectorized)
// ---------------------------------------------------------------------------
__global__ void __launch_bounds__(256) gather_kernel(int N) {
  int w = (blockIdx.x * blockDim.x + threadIdx.x) >> 5;
  int lane = threadIdx.x & 31;
  if (w >= N) return;
  int s = __ldg(&g_rowstart[w]);
  int e = __ldg(&g_rowend[w]);
  int sub = lane >> 3, ch = lane & 7;

  float acc[8];
#pragma unroll
  for (int i = 0; i < 8; i++) acc[i] = 0.f;

  for (int j = s + sub; j < e; j += 4) {
    int src = __ldg(&g_csrsrc[j]);
    uint4 v = __ldg((const uint4*)((const char*)g_Mh4 + (size_t)src * 128) +
                    ch);
    const __half2* hp = (const __half2*)&v;
#pragma unroll
    for (int q = 0; q < 4; q++) {
      float2 f = __half22float2(hp[q]);
      acc[2 * q + 0] += f.x;
      acc[2 * q + 1] += f.y;
    }
  }
#pragma unroll
  for (int i = 0; i < 8; i++) {
    acc[i] += __shfl_xor_sync(0xffffffffu, acc[i], 8);
    acc[i] += __shfl_xor_sync(0xffffffffu, acc[i], 16);
  }
  if (lane < 8) {
    float* ag = (float*)g_agg4f + (size_t)w * 64 + lane * 8;
    ((float4*)ag)[0] = make_float4(acc[0], acc[1], acc[2], acc[3]);
    ((float4*)ag)[1] = make_float4(acc[4], acc[5], acc[6], acc[7]);
  }
}

// Common staging: W1 (wh+0), W2 (wh+4096), A = split h. 128-row tile.
#define STAGE_COMMON()                                                       \
  for (int j = tid; j < 512; j += 256) {                                     \
    int k = j >> 3, ch = j & 7;                                              \
    *(uint4*)((char*)w1h + k * 144 + ch * 16) = __ldg((const uint4*)wh + j); \
    *(uint4*)((char*)w1l + k * 144 + ch * 16) = __ldg((const uint4*)wl + j); \
    *(uint4*)((char*)w2h + k * 144 + ch * 16) =                              \
        __ldg((const uint4*)(wh + 4096) + j);                                \
    *(uint4*)((char*)w2l + k * 144 + ch * 16) =                              \
        __ldg((const uint4*)(wl + 4096) + j);                                \
  }                                                                          \
  for (int j = tid; j < 1024; j += 256) {                                    \
    int r = j >> 3, ch = j & 7;                                              \
    int grow = rb + r;                                                       \
    uint4 vh = make_uint4(0, 0, 0, 0), vl = make_uint4(0, 0, 0, 0);          \
    if (grow < N) {                                                          \
      vh = __ldg((const uint4*)((const char*)g_hh4 + (size_t)grow * 128) +   \
                 ch);                                                        \
      vl = __ldg((const uint4*)((const char*)g_hl4 + (size_t)grow * 128) +   \
                 ch);                                                        \
    }                                                                        \
    *(uint4*)((char*)a_hi + r * 144 + ch * 16) = vh;                         \
    *(uint4*)((char*)a_lo + r * 144 + ch * 16) = vl;                         \
  }

// Shared fragment-index setup for the chained-GEMM kernels.
// Warp tile: 16 rows x 64 cols; warp w owns rows w*16 .. w*16+15.
#define FRAG_SETUP()                                                         \
  int lane = tid & 31, wpi = tid >> 5;                                       \
  int g = lane >> 2, tg = lane & 3;                                          \
  int r0w = wpi * 16;                                                        \
  int a_row = r0w + (lane & 15);                                             \
  int a_koff = (lane >> 4) * 8;                                              \
  int b_krow = (lane & 7) + ((lane >> 3) & 1) * 8;                           \
  int b_noff = (lane >> 4) * 8;

// One k-chunk of a 3-term-split GEMM stage with A fragments in registers.
#define STAGE2_CHUNK(WBASE, KC)                                              \
  {                                                                          \
    _Pragma("unroll") for (int jj = 0; jj < 4; jj++) {                       \
      uint32_t bh[4], bl[4];                                                 \
      const __half* bp =                                                     \
          (WBASE) + ((KC)*16 + b_krow) * 72 + jj * 16 + b_noff;              \
      ldsm4t(bp, bh);                                                        \
      ldsm4t(bp + 64 * 72, bl);                                              \
      mma16816(acc[2 * jj], thi[KC], bh);                                    \
      mma16816(acc[2 * jj], tlo[KC], bh);                                    \
      mma16816(acc[2 * jj], thi[KC], bl);                                    \
      mma16816(acc[2 * jj + 1], thi[KC], bh + 2);                            \
      mma16816(acc[2 * jj + 1], tlo[KC], bh + 2);                            \
      mma16816(acc[2 * jj + 1], thi[KC], bl + 2);                            \
    }                                                                        \
  }

#define STAGE1_LOOP(WBASE)                                                   \
  _Pragma("unroll") for (int kc = 0; kc < 64; kc += 16) {                    \
    uint32_t ah[4], al[4];                                                   \
    ldsm4(a_hi + a_row * 72 + kc + a_koff, ah);                              \
    ldsm4(a_lo + a_row * 72 + kc + a_koff, al);                              \
    _Pragma("unroll") for (int jj = 0; jj < 4; jj++) {                       \
      uint32_t bh[4], bl[4];                                                 \
      const __half* bp = (WBASE) + (kc + b_krow) * 72 + jj * 16 + b_noff;    \
      ldsm4t(bp, bh);                                                        \
      ldsm4t(bp + 64 * 72, bl);                                              \
      mma16816(acc[2 * jj], ah, bh);                                         \
      mma16816(acc[2 * jj], al, bh);                                         \
      mma16816(acc[2 * jj], ah, bl);                                         \
      mma16816(acc[2 * jj + 1], ah, bh + 2);                                 \
      mma16816(acc[2 * jj + 1], al, bh + 2);                                 \
      mma16816(acc[2 * jj + 1], ah, bl + 2);                                 \
    }                                                                        \
  }

#define ZERO_ACC()                                                           \
  _Pragma("unroll") for (int j = 0; j < 8; j++)                              \
      _Pragma("unroll") for (int q = 0; q < 4; q++) acc[j][q] = 0.f;

// ---------------------------------------------------------------------------
// msg: M'' = relu(h @ W1 + b1) @ V + c.  Register-chained mma.m16n8k16,
// 128-row block tile, 16x64 warp tiles, ONE barrier.
// ---------------------------------------------------------------------------
__global__ void __launch_bounds__(256, 2) msg_kernel(
    const __half* __restrict__ wh, const __half* __restrict__ wl,
    const float* __restrict__ B1, const float* __restrict__ CB, int N) {
  extern __shared__ char smc[];
  __half* a_hi = (__half*)smc;       // 128 x 72
  __half* a_lo = a_hi + 128 * 72;
  __half* w1h = a_lo + 128 * 72;     // 64 x 72
  __half* w1l = w1h + 64 * 72;
  __half* w2h = w1l + 64 * 72;       // V
  __half* w2l = w2h + 64 * 72;
  __shared__ float sb1[64], sb2[64];

  int tid = threadIdx.x;
  int rb = blockIdx.x * 128;

  STAGE_COMMON();
  if (tid < 64) {
    sb1[tid] = __ldg(B1 + tid);
    sb2[tid] = __ldg(CB + tid);
  }
  __syncthreads();

  FRAG_SETUP();
  float acc[8][4];
  ZERO_ACC();
  STAGE1_LOOP(w1h);

  // t = relu(acc + b1) in registers -> A' fragments (split hi/lo)
  uint32_t thi[4][4], tlo[4][4];
#pragma unroll
  for (int j = 0; j < 8; j++) {
    int cA = 8 * j + 2 * tg;
    float f0 = fmaxf(acc[j][0] + sb1[cA], 0.f);
    float f1 = fmaxf(acc[j][1] + sb1[cA + 1], 0.f);
    float f2 = fmaxf(acc[j][2] + sb1[cA], 0.f);
    float f3 = fmaxf(acc[j][3] + sb1[cA + 1], 0.f);
    int kc = j >> 1, o = (j & 1) * 2;
    splitpack2(f0, f1, thi[kc][o], tlo[kc][o]);
    splitpack2(f2, f3, thi[kc][o + 1], tlo[kc][o + 1]);
  }

  ZERO_ACC();
#pragma unroll
  for (int kc = 0; kc < 4; kc++) STAGE2_CHUNK(w2h, kc);

  // M'' = acc + c  (fp16, straight to global from C-layout registers)
  int row0 = rb + r0w + g, row1 = row0 + 8;
#pragma unroll
  for (int j = 0; j < 8; j++) {
    int cA = 8 * j + 2 * tg;
    if (row0 < N)
      *(__half2*)((__half*)g_Mh4 + (size_t)row0 * 64 + cA) =
          __floats2half2_rn(acc[j][0] + sb2[cA], acc[j][1] + sb2[cA + 1]);
    if (row1 < N)
      *(__half2*)((__half*)g_Mh4 + (size_t)row1 * 64 + cA) =
          __floats2half2_rn(acc[j][2] + sb2[cA], acc[j][3] + sb2[cA + 1]);
  }
}

// ---------------------------------------------------------------------------
// upd: t = relu(h @ W1a + agg'' + b1); hn = t @ W2 + b2; bn; h = relu(hn+h)
// Same register-chained structure, ONE barrier.
// ---------------------------------------------------------------------------
__global__ void __launch_bounds__(256, 2) upd_kernel(
    const __half* __restrict__ wh, const __half* __restrict__ wl,
    const float* __restrict__ B1, const float* __restrict__ B2,
    const float* __restrict__ Gm, const float* __restrict__ Bt,
    const float* __restrict__ Mn, const float* __restrict__ Vr, int N) {
  extern __shared__ char smc[];
  __half* a_hi = (__half*)smc;       // 128 x 72
  __half* a_lo = a_hi + 128 * 72;
  __half* w1h = a_lo + 128 * 72;     // W1a
  __half* w1l = w1h + 64 * 72;
  __half* w2h = w1l + 64 * 72;       // W2
  __half* w2l = w2h + 64 * 72;
  __shared__ float sb1[64], b2s[64], scs[64], shs[64];

  int tid = threadIdx.x;
  int rb = blockIdx.x * 128;

  STAGE_COMMON();
  if (tid < 64) {
    float s = __ldg(Gm + tid) * rsqrtf(__ldg(Vr + tid) + 1e-5f);
    scs[tid] = s;
    shs[tid] = __ldg(Bt + tid) - __ldg(Mn + tid) * s;
    sb1[tid] = __ldg(B1 + tid);
    b2s[tid] = __ldg(B2 + tid);
  }
  __syncthreads();

  FRAG_SETUP();
  float acc[8][4];
  ZERO_ACC();
  STAGE1_LOOP(w1h);

  int row0 = rb + r0w + g, row1 = row0 + 8;
  const float* aggp = (const float*)g_agg4f;

  // t = relu(acc + agg'' + b1) in registers -> A' fragments (split hi/lo)
  uint32_t thi[4][4], tlo[4][4];
#pragma unroll
  for (int j = 0; j < 8; j++) {
    int cA = 8 * j + 2 * tg;
    float2 ag01 = (row0 < N)
                      ? *(const float2*)(aggp + (size_t)row0 * 64 + cA)
                      : make_float2(0.f, 0.f);
    float2 ag23 = (row1 < N)
                      ? *(const float2*)(aggp + (size_t)row1 * 64 + cA)
                      : make_float2(0.f, 0.f);
    float f0 = fmaxf(acc[j][0] + ag01.x + sb1[cA], 0.f);
    float f1 = fmaxf(acc[j][1] + ag01.y + sb1[cA + 1], 0.f);
    float f2 = fmaxf(acc[j][2] + ag23.x + sb1[cA], 0.f);
    float f3 = fmaxf(acc[j][3] + ag23.y + sb1[cA + 1], 0.f);
    int kc = j >> 1, o = (j & 1) * 2;
    splitpack2(f0, f1, thi[kc][o], tlo[kc][o]);
    splitpack2(f2, f3, thi[kc][o + 1], tlo[kc][o + 1]);
  }

  ZERO_ACC();
#pragma unroll
  for (int kc = 0; kc < 4; kc++) STAGE2_CHUNK(w2h, kc);

  // h = relu(bn(acc + b2) + h_old); h_old = hi+lo from global (exact);
  // write split h back.
#pragma unroll
  for (int j = 0; j < 8; j++) {
    int cA = 8 * j + 2 * tg;
    if (row0 < N) {
      __half2 hh = *(const __half2*)((const __half*)g_hh4 +
                                     (size_t)row0 * 64 + cA);
      __half2 hl = *(const __half2*)((const __half*)g_hl4 +
                                     (size_t)row0 * 64 + cA);
      float2 fh = __half22float2(hh), fl = __half22float2(hl);
      float v0 = acc[j][0] + b2s[cA];
      float v1 = acc[j][1] + b2s[cA + 1];
      float o0 = fmaxf(fmaf(v0, scs[cA], shs[cA]) + fh.x + fl.x, 0.f);
      float o1 =
          fmaxf(fmaf(v1, scs[cA + 1], shs[cA + 1]) + fh.y + fl.y, 0.f);
      uint32_t ph, pl;
      splitpack2(o0, o1, ph, pl);
      *(uint32_t*)((__half*)g_hh4 + (size_t)row0 * 64 + cA) = ph;
      *(uint32_t*)((__half*)g_hl4 + (size_t)row0 * 64 + cA) = pl;
    }
    if (row1 < N) {
      __half2 hh = *(const __half2*)((const __half*)g_hh4 +
                                     (size_t)row1 * 64 + cA);
      __half2 hl = *(const __half2*)((const __half*)g_hl4 +
                                     (size_t)row1 * 64 + cA);
      float2 fh = __half22float2(hh), fl = __half22float2(hl);
      float v2 = acc[j][2] + b2s[cA];
      float v3 = acc[j][3] + b2s[cA + 1];
      float o2 = fmaxf(fmaf(v2, scs[cA], shs[cA]) + fh.x + fl.x, 0.f);
      float o3 =
          fmaxf(fmaf(v3, scs[cA + 1], shs[cA + 1]) + fh.y + fl.y, 0.f);
      uint32_t ph, pl;
      splitpack2(o2, o3, ph, pl);
      *(uint32_t*)((__half*)g_hh4 + (size_t)row1 * 64 + cA) = ph;
      *(uint32_t*)((__half*)g_hl4 + (size_t)row1 * 64 + cA) = pl;
    }
  }
}

// ---------------------------------------------------------------------------
// out = relu(h[:NQ] @ out_w1 + b1) @ out_w2 + b2   (warp per node)
// ---------------------------------------------------------------------------
__global__ void __launch_bounds__(256) out_kernel(
    const float* __restrict__ w1, const float* __restrict__ b1,
    const float* __restrict__ w2, const float* __restrict__ b2,
    float* __restrict__ out, int NQ) {
  int warp = (blockIdx.x * blockDim.x + threadIdx.x) >> 5;
  int lane = threadIdx.x & 31;
  if (warp >= NQ) return;
  float2 hh = __half22float2(((const __half2*)g_hh4)[(size_t)warp * 32 + lane]);
  float2 hl = __half22float2(((const __half2*)g_hl4)[(size_t)warp * 32 + lane]);
  float2 hv = make_float2(hh.x + hl.x, hh.y + hl.y);
  float acc = __ldg(b1 + lane);
#pragma unroll
  for (int kk = 0; kk < 32; kk++) {
    float hx = __shfl_sync(0xffffffffu, hv.x, kk);
    float hy = __shfl_sync(0xffffffffu, hv.y, kk);
    acc = fmaf(hx, __ldg(w1 + (2 * kk) * 32 + lane), acc);
    acc = fmaf(hy, __ldg(w1 + (2 * kk + 1) * 32 + lane), acc);
  }
  float v = fmaxf(acc, 0.f) * __ldg(w2 + lane);
#pragma unroll
  for (int o = 16; o; o >>= 1) v += __shfl_down_sync(0xffffffffu, v, o);
  if (lane == 0) out[warp] = v + __ldg(b2);
}

// ---------------------------------------------------------------------------
extern "C" void kernel_launch(void* const* d_in, const int* in_sizes, int n_in,
                              void* d_out, int out_size) {
  int off = (n_in >= 21) ? 1 : 0;
  const float* x      = (const float*)d_in[0];
  const int*   ei     = (const int*)d_in[1];
  const float* w_in   = (const float*)d_in[2 + off];
  const float* b_in   = (const float*)d_in[3 + off];
  const float* msg_w1 = (const float*)d_in[4 + off];
  const float* msg_b1 = (const float*)d_in[5 + off];
  const float* msg_w2 = (const float*)d_in[6 + off];
  const float* msg_b2 = (const float*)d_in[7 + off];
  const float* upd_w1 = (const float*)d_in[8 + off];
  const float* upd_b1 = (const float*)d_in[9 + off];
  const float* upd_w2 = (const float*)d_in[10 + off];
  const float* upd_b2 = (const float*)d_in[11 + off];
  const float* bn_g   = (const float*)d_in[12 + off];
  const float* bn_b   = (const float*)d_in[13 + off];
  const float* bn_m   = (const float*)d_in[14 + off];
  const float* bn_v   = (const float*)d_in[15 + off];
  const float* out_w1 = (const float*)d_in[16 + off];
  const float* out_b1 = (const float*)d_in[17 + off];
  const float* out_w2 = (const float*)d_in[18 + off];
  const float* out_b2 = (const float*)d_in[19 + off];

  int N = in_sizes[0] / 3;
  int E = in_sizes[1] / 2;
  int L = in_sizes[4 + off] / (64 * 64);
  int NQ = out_size;

  const int GEMM_SMEM = (2 * 128 * 72 + 4 * 64 * 72) * 2;  // 73,728 B
  cudaFuncSetAttribute(msg_kernel, cudaFuncAttributeMaxDynamicSharedMemorySize,
                       GEMM_SMEM);
  cudaFuncSetAttribute(upd_kernel, cudaFuncAttributeMaxDynamicSharedMemorySize,
                       GEMM_SMEM);

  int gb = (N + 127) / 128;
  int nb_scan = (N + 1023) / 1024;

  void* whp = nullptr;
  void* wlp = nullptr;
  void* cbp = nullptr;
  cudaGetSymbolAddress(&whp, g_wh4);
  cudaGetSymbolAddress(&wlp, g_wl4);
  cudaGetSymbolAddress(&cbp, g_cb);
  const __half* wh = (const __half*)whp;
  const __half* wl = (const __half*)wlp;
  const float* cb = (const float*)cbp;

  // Order: wsplit(1), wfuse(2), input(3), msg0(4) <- profiled slot, ...
  wprep_split_kernel<<<(L * 12288 + 255) / 256, 256>>>(msg_w1, upd_w1, upd_w2,
                                                       L);
  wprep_fuse_kernel<<<L, 256>>>(msg_w2, upd_w1, msg_b2);
  input_kernel<<<(N * 64 + 255) / 256, 256>>>(x, w_in, b_in, N);
  msg_kernel<<<gb, 256, GEMM_SMEM>>>(wh, wl, msg_b1, cb, N);
  zero_counts_kernel<<<(N + 255) / 256, 256>>>(N);
  hist_kernel<<<(E + 255) / 256, 256>>>(ei, E);
  scan1_kernel<<<nb_scan, 1024>>>(N);
  scan2_kernel<<<1, 128>>>(nb_scan);
  scan3_kernel<<<(N + 255) / 256, 256>>>(N);
  fill_kernel<<<(E + 255) / 256, 256>>>(ei, E);

  for (int l = 0; l < L; l++) {
    if (l > 0)
      msg_kernel<<<gb, 256, GEMM_SMEM>>>(wh + l * 16384, wl + l * 16384,
                                         msg_b1 + l * 64, cb + l * 64, N);
    gather_kernel<<<(N * 32 + 255) / 256, 256>>>(N);
    upd_kernel<<<gb, 256, GEMM_SMEM>>>(
        wh + l * 16384 + 8192, wl + l * 16384 + 8192, upd_b1 + l * 64,
        upd_b2 + l * 64, bn_g + l * 64, bn_b + l * 64, bn_m + l * 64,
        bn_v + l * 64, N);
  }

  out_kernel<<<(NQ * 32 + 255) / 256, 256>>>(out_w1, out_b1, out_w2, out_b2,
                                             (float*)d_out, NQ);
}

// round 15
// speedup vs baseline: 1.1780x; 1.0306x over previous
#include <cuda_runtime.h>
#include <cuda_fp16.h>
#include <cstdint>

#define MAXN 100000
#define MAXE 1600000
#define MAXL 8

// Persistent scratch (no allocations allowed).
__device__ float4 g_hh4[MAXN * 8];     // h hi (half, N x 64)
__device__ float4 g_hl4[MAXN * 8];     // h lo
__device__ float4 g_Mh4[MAXN * 8];     // M'' (fp16, N x 64)
__device__ float4 g_agg4f[(MAXN + 128) * 16];  // agg'' (fp32, N x 64)
__device__ float4 g_wh4[MAXL * 2048];  // weights hi: 16384 half / layer
__device__ float4 g_wl4[MAXL * 2048];  // weights lo: 16384 half / layer
__device__ float g_cb[MAXL * 64];      // fused bias c = b2 @ updW1b
// CSR
__device__ int g_counts[MAXN];
__device__ int g_rowstart[MAXN];
__device__ int g_rowend[MAXN];
__device__ int g_csrsrc[MAXE];
__device__ int g_blocksum[128];

__device__ __forceinline__ void split2(float x, __half& hi, __half& lo) {
  hi = __float2half_rn(x);
  lo = __float2half_rn(x - __half2float(hi));
}

__device__ __forceinline__ void splitpack2(float x, float y, uint32_t& hi,
                                           uint32_t& lo) {
  __half hx, lx, hy, ly;
  split2(x, hx, lx);
  split2(y, hy, ly);
  __half2 ph = __halves2half2(hx, hy), pl = __halves2half2(lx, ly);
  hi = *(uint32_t*)&ph;
  lo = *(uint32_t*)&pl;
}

__device__ __forceinline__ uint32_t sm32(const void* p) {
  return (uint32_t)__cvta_generic_to_shared(p);
}
__device__ __forceinline__ void ldsm4(const void* p, uint32_t* r) {
  asm volatile(
      "ldmatrix.sync.aligned.m8n8.x4.shared.b16 {%0,%1,%2,%3}, [%4];"
      : "=r"(r[0]), "=r"(r[1]), "=r"(r[2]), "=r"(r[3])
      : "r"(sm32(p)));
}
__device__ __forceinline__ void ldsm4t(const void* p, uint32_t* r) {
  asm volatile(
      "ldmatrix.sync.aligned.m8n8.x4.trans.shared.b16 {%0,%1,%2,%3}, [%4];"
      : "=r"(r[0]), "=r"(r[1]), "=r"(r[2]), "=r"(r[3])
      : "r"(sm32(p)));
}
__device__ __forceinline__ void mma16816(float* c, const uint32_t* a,
                                         const uint32_t* b) {
  asm volatile(
      "mma.sync.aligned.m16n8k16.row.col.f32.f16.f16.f32 "
      "{%0,%1,%2,%3}, {%4,%5,%6,%7}, {%8,%9}, {%0,%1,%2,%3};"
      : "+f"(c[0]), "+f"(c[1]), "+f"(c[2]), "+f"(c[3])
      : "r"(a[0]), "r"(a[1]), "r"(a[2]), "r"(a[3]), "r"(b[0]), "r"(b[1]));
}

// ---------------------------------------------------------------------------
// wprep_split: copy+split msgW1 -> [0,4096), updW1a -> [8192,12288),
// updW2 -> [12288,16384). (V fills [4096,8192) in wprep_fuse.)
// ---------------------------------------------------------------------------
__global__ void __launch_bounds__(256) wprep_split_kernel(
    const float* __restrict__ mw1, const float* __restrict__ uw1,
    const float* __restrict__ uw2, int L) {
  int i = blockIdx.x * blockDim.x + threadIdx.x;
  if (i >= L * 12288) return;
  int l = i / 12288, off = i % 12288;
  int seg = off >> 12, r = off & 4095;
  float v;
  int dst;
  if (seg == 0) {
    v = __ldg(mw1 + l * 4096 + r);
    dst = l * 16384 + r;
  } else if (seg == 1) {
    v = __ldg(uw1 + l * 8192 + r);  // rows [0,64) = W1a
    dst = l * 16384 + 8192 + r;
  } else {
    v = __ldg(uw2 + l * 4096 + r);
    dst = l * 16384 + 12288 + r;
  }
  __half hi, lo;
  split2(v, hi, lo);
  ((__half*)g_wh4)[dst] = hi;
  ((__half*)g_wl4)[dst] = lo;
}

// ---------------------------------------------------------------------------
// wprep_fuse: V = msgW2 @ updW1b (64x64, fp32), c = msg_b2 @ updW1b.
// ---------------------------------------------------------------------------
__global__ void __launch_bounds__(256) wprep_fuse_kernel(
    const float* __restrict__ mw2, const float* __restrict__ uw1,
    const float* __restrict__ mb2) {
  __shared__ float su[4096];  // updW1b (rows [64,128) of uw1)
  __shared__ float sw[4096];  // msgW2
  int l = blockIdx.x, t = threadIdx.x;
  for (int i = t; i < 4096; i += 256) {
    su[i] = __ldg(uw1 + l * 8192 + 4096 + i);
    sw[i] = __ldg(mw2 + l * 4096 + i);
  }
  __syncthreads();
  for (int e = t; e < 4096; e += 256) {
    int k = e >> 6, n = e & 63;
    float s = 0.f;
#pragma unroll 8
    for (int j = 0; j < 64; j++) s += sw[k * 64 + j] * su[j * 64 + n];
    __half hi, lo;
    split2(s, hi, lo);
    ((__half*)g_wh4)[l * 16384 + 4096 + e] = hi;
    ((__half*)g_wl4)[l * 16384 + 4096 + e] = lo;
  }
  if (t < 64) {
    float s = 0.f;
#pragma unroll 8
    for (int j = 0; j < 64; j++) s += __ldg(mb2 + l * 64 + j) * su[j * 64 + t];
    g_cb[l * 64 + t] = s;
  }
}

// ---------------------------------------------------------------------------
// h = relu(x @ w_in + b_in), stored split
// ---------------------------------------------------------------------------
__global__ void __launch_bounds__(256) input_kernel(
    const float* __restrict__ x, const float* __restrict__ w_in,
    const float* __restrict__ b_in, int N) {
  int i = blockIdx.x * blockDim.x + threadIdx.x;
  if (i >= N * 64) return;
  int node = i >> 6, c = i & 63;
  float acc = __ldg(b_in + c);
  acc = fmaf(__ldg(x + node * 3 + 0), __ldg(w_in + c), acc);
  acc = fmaf(__ldg(x + node * 3 + 1), __ldg(w_in + 64 + c), acc);
  acc = fmaf(__ldg(x + node * 3 + 2), __ldg(w_in + 128 + c), acc);
  float h = fmaxf(acc, 0.f);
  __half hi, lo;
  split2(h, hi, lo);
  ((__half*)g_hh4)[i] = hi;
  ((__half*)g_hl4)[i] = lo;
}

// ---------------------------------------------------------------------------
// CSR build
// ---------------------------------------------------------------------------
__global__ void __launch_bounds__(256) zero_counts_kernel(int N) {
  int i = blockIdx.x * blockDim.x + threadIdx.x;
  if (i < N) g_counts[i] = 0;
}

__global__ void __launch_bounds__(256) hist_kernel(const int* __restrict__ ei,
                                                   int E) {
  int e = blockIdx.x * blockDim.x + threadIdx.x;
  if (e < E) atomicAdd(&g_counts[__ldg(ei + E + e)], 1);
}

__global__ void __launch_bounds__(1024) scan1_kernel(int N) {
  __shared__ int sh[1024];
  int t = threadIdx.x;
  int idx = blockIdx.x * 1024 + t;
  int v = (idx < N) ? g_counts[idx] : 0;
  sh[t] = v;
  __syncthreads();
#pragma unroll
  for (int off = 1; off < 1024; off <<= 1) {
    int x = (t >= off) ? sh[t - off] : 0;
    __syncthreads();
    sh[t] += x;
    __syncthreads();
  }
  if (idx < N) g_rowstart[idx] = sh[t] - v;
  if (t == 1023) g_blocksum[blockIdx.x] = sh[1023];
}

__global__ void __launch_bounds__(128) scan2_kernel(int nb) {
  __shared__ int sh[128];
  int t = threadIdx.x;
  int v = (t < nb) ? g_blocksum[t] : 0;
  sh[t] = v;
  __syncthreads();
#pragma unroll
  for (int off = 1; off < 128; off <<= 1) {
    int x = (t >= off) ? sh[t - off] : 0;
    __syncthreads();
    sh[t] += x;
    __syncthreads();
  }
  if (t < nb) g_blocksum[t] = sh[t] - v;
}

__global__ void __launch_bounds__(256) scan3_kernel(int N) {
  int i = blockIdx.x * blockDim.x + threadIdx.x;
  if (i < N) {
    int v = g_rowstart[i] + g_blocksum[i >> 10];
    g_rowstart[i] = v;
    g_rowend[i] = v;
  }
}

__global__ void __launch_bounds__(256) fill_kernel(const int* __restrict__ ei,
                                                   int E) {
  int e = blockIdx.x * blockDim.x + threadIdx.x;
  if (e < E) {
    int d = __ldg(ei + E + e);
    int pos = atomicAdd(&g_rowend[d], 1);
    g_csrsrc[pos] = __ldg(ei + e);
  }
}

// ---------------------------------------------------------------------------
// agg''[i] = sum_{e: dst(e)=i} M''[src(e)]   (warp per node, vectorized,
// edge loop unrolled x2 for MLP)
// ---------------------------------------------------------------------------
__global__ void __launch_bounds__(256) gather_kernel(int N) {
  int w = (blockIdx.x * blockDim.x + threadIdx.x) >> 5;
  int lane = threadIdx.x & 31;
  if (w >= N) return;
  int s = __ldg(&g_rowstart[w]);
  int e = __ldg(&g_rowend[w]);
  int sub = lane >> 3, ch = lane & 7;

  float acc[8];
#pragma unroll
  for (int i = 0; i < 8; i++) acc[i] = 0.f;

  int j = s + sub;
  for (; j + 4 < e; j += 8) {
    int src0 = __ldg(&g_csrsrc[j]);
    int src1 = __ldg(&g_csrsrc[j + 4]);
    uint4 v0 = __ldg((const uint4*)((const char*)g_Mh4 + (size_t)src0 * 128) +
                     ch);
    uint4 v1 = __ldg((const uint4*)((const char*)g_Mh4 + (size_t)src1 * 128) +
                     ch);
    const __half2* h0 = (const __half2*)&v0;
    const __half2* h1 = (const __half2*)&v1;
#pragma unroll
    for (int q = 0; q < 4; q++) {
      float2 f0 = __half22float2(h0[q]);
      float2 f1 = __half22float2(h1[q]);
      acc[2 * q + 0] += f0.x + f1.x;
      acc[2 * q + 1] += f0.y + f1.y;
    }
  }
  if (j < e) {
    int src0 = __ldg(&g_csrsrc[j]);
    uint4 v0 = __ldg((const uint4*)((const char*)g_Mh4 + (size_t)src0 * 128) +
                     ch);
    const __half2* h0 = (const __half2*)&v0;
#pragma unroll
    for (int q = 0; q < 4; q++) {
      float2 f0 = __half22float2(h0[q]);
      acc[2 * q + 0] += f0.x;
      acc[2 * q + 1] += f0.y;
    }
  }
#pragma unroll
  for (int i = 0; i < 8; i++) {
    acc[i] += __shfl_xor_sync(0xffffffffu, acc[i], 8);
    acc[i] += __shfl_xor_sync(0xffffffffu, acc[i], 16);
  }
  if (lane < 8) {
    float* ag = (float*)g_agg4f + (size_t)w * 64 + lane * 8;
    ((float4*)ag)[0] = make_float4(acc[0], acc[1], acc[2], acc[3]);
    ((float4*)ag)[1] = make_float4(acc[4], acc[5], acc[6], acc[7]);
  }
}

// Stage one 64x64 weight pair (hi/lo) from global into smem (stride 72).
#define STAGE_W(DSTH, DSTL, SRCH, SRCL)                                      \
  for (int j = tid; j < 512; j += 256) {                                     \
    int k = j >> 3, ch = j & 7;                                              \
    *(uint4*)((char*)(DSTH) + k * 144 + ch * 16) =                           \
        __ldg((const uint4*)(SRCH) + j);                                     \
    *(uint4*)((char*)(DSTL) + k * 144 + ch * 16) =                           \
        __ldg((const uint4*)(SRCL) + j);                                     \
  }

// Stage split-h rows rb..rb+127 into a_hi/a_lo.
#define STAGE_A()                                                            \
  for (int j = tid; j < 1024; j += 256) {                                    \
    int r = j >> 3, ch = j & 7;                                              \
    int grow = rb + r;                                                       \
    uint4 vh = make_uint4(0, 0, 0, 0), vl = make_uint4(0, 0, 0, 0);          \
    if (grow < N) {                                                          \
      vh = __ldg((const uint4*)((const char*)g_hh4 + (size_t)grow * 128) +   \
                 ch);                                                        \
      vl = __ldg((const uint4*)((const char*)g_hl4 + (size_t)grow * 128) +   \
                 ch);                                                        \
    }                                                                        \
    *(uint4*)((char*)a_hi + r * 144 + ch * 16) = vh;                         \
    *(uint4*)((char*)a_lo + r * 144 + ch * 16) = vl;                         \
  }

// Shared fragment-index setup for the chained-GEMM kernels.
#define FRAG_SETUP()                                                         \
  int lane = tid & 31, wpi = tid >> 5;                                       \
  int g = lane >> 2, tg = lane & 3;                                          \
  int r0w = wpi * 16;                                                        \
  int a_row = r0w + (lane & 15);                                             \
  int a_koff = (lane >> 4) * 8;                                              \
  int b_krow = (lane & 7) + ((lane >> 3) & 1) * 8;                           \
  int b_noff = (lane >> 4) * 8;

// One k-chunk of a 3-term-split GEMM stage with A fragments in registers.
#define STAGE2_CHUNK(WBASE, KC)                                              \
  {                                                                          \
    _Pragma("unroll") for (int jj = 0; jj < 4; jj++) {                       \
      uint32_t bh[4], bl[4];                                                 \
      const __half* bp =                                                     \
          (WBASE) + ((KC)*16 + b_krow) * 72 + jj * 16 + b_noff;              \
      ldsm4t(bp, bh);                                                        \
      ldsm4t(bp + 64 * 72, bl);                                              \
      mma16816(acc[2 * jj], thi[KC], bh);                                    \
      mma16816(acc[2 * jj], tlo[KC], bh);                                    \
      mma16816(acc[2 * jj], thi[KC], bl);                                    \
      mma16816(acc[2 * jj + 1], thi[KC], bh + 2);                            \
      mma16816(acc[2 * jj + 1], tlo[KC], bh + 2);                            \
      mma16816(acc[2 * jj + 1], thi[KC], bl + 2);                            \
    }                                                                        \
  }

#define STAGE1_LOOP(WBASE)                                                   \
  _Pragma("unroll") for (int kc = 0; kc < 64; kc += 16) {                    \
    uint32_t ah[4], al[4];                                                   \
    ldsm4(a_hi + a_row * 72 + kc + a_koff, ah);                              \
    ldsm4(a_lo + a_row * 72 + kc + a_koff, al);                              \
    _Pragma("unroll") for (int jj = 0; jj < 4; jj++) {                       \
      uint32_t bh[4], bl[4];                                                 \
      const __half* bp = (WBASE) + (kc + b_krow) * 72 + jj * 16 + b_noff;    \
      ldsm4t(bp, bh);                                                        \
      ldsm4t(bp + 64 * 72, bl);                                              \
      mma16816(acc[2 * jj], ah, bh);                                         \
      mma16816(acc[2 * jj], al, bh);                                         \
      mma16816(acc[2 * jj], ah, bl);                                         \
      mma16816(acc[2 * jj + 1], ah, bh + 2);                                 \
      mma16816(acc[2 * jj + 1], al, bh + 2);                                 \
      mma16816(acc[2 * jj + 1], ah, bl + 2);                                 \
    }                                                                        \
  }

#define ZERO_ACC()                                                           \
  _Pragma("unroll") for (int j = 0; j < 8; j++)                              \
      _Pragma("unroll") for (int q = 0; q < 4; q++) acc[j][q] = 0.f;

// Write M'' = acc + bias (fp16) straight to global from C-layout registers.
#define M_EPILOGUE(BIAS)                                                     \
  _Pragma("unroll") for (int j = 0; j < 8; j++) {                            \
    int cA = 8 * j + 2 * tg;                                                 \
    if (row0 < N)                                                            \
      *(__half2*)((__half*)g_Mh4 + (size_t)row0 * 64 + cA) =                 \
          __floats2half2_rn(acc[j][0] + (BIAS)[cA],                          \
                            acc[j][1] + (BIAS)[cA + 1]);                     \
    if (row1 < N)                                                            \
      *(__half2*)((__half*)g_Mh4 + (size_t)row1 * 64 + cA) =                 \
          __floats2half2_rn(acc[j][2] + (BIAS)[cA],                          \
                            acc[j][3] + (BIAS)[cA + 1]);                     \
  }

// msg t-epilogue: thi/tlo = split(relu(acc + b1))
#define T_EPILOGUE_MSG(B1S)                                                  \
  _Pragma("unroll") for (int j = 0; j < 8; j++) {                            \
    int cA = 8 * j + 2 * tg;                                                 \
    float f0 = fmaxf(acc[j][0] + (B1S)[cA], 0.f);                            \
    float f1 = fmaxf(acc[j][1] + (B1S)[cA + 1], 0.f);                        \
    float f2 = fmaxf(acc[j][2] + (B1S)[cA], 0.f);                            \
    float f3 = fmaxf(acc[j][3] + (B1S)[cA + 1], 0.f);                        \
    int kc = j >> 1, o = (j & 1) * 2;                                        \
    splitpack2(f0, f1, thi[kc][o], tlo[kc][o]);                              \
    splitpack2(f2, f3, thi[kc][o + 1], tlo[kc][o + 1]);                      \
  }

// ---------------------------------------------------------------------------
// msg: M'' = relu(h @ W1 + b1) @ V + c.  Register-chained mma.m16n8k16.
// ---------------------------------------------------------------------------
__global__ void __launch_bounds__(256, 2) msg_kernel(
    const __half* __restrict__ wh, const __half* __restrict__ wl,
    const float* __restrict__ B1, const float* __restrict__ CB, int N) {
  extern __shared__ char smc[];
  __half* a_hi = (__half*)smc;       // 128 x 72
  __half* a_lo = a_hi + 128 * 72;
  __half* w1h = a_lo + 128 * 72;     // 64 x 72
  __half* w1l = w1h + 64 * 72;
  __half* w2h = w1l + 64 * 72;       // V
  __half* w2l = w2h + 64 * 72;
  __shared__ float sb1[64], sb2[64];

  int tid = threadIdx.x;
  int rb = blockIdx.x * 128;

  STAGE_W(w1h, w1l, wh, wl);
  STAGE_W(w2h, w2l, wh + 4096, wl + 4096);
  STAGE_A();
  if (tid < 64) {
    sb1[tid] = __ldg(B1 + tid);
    sb2[tid] = __ldg(CB + tid);
  }
  __syncthreads();

  FRAG_SETUP();
  float acc[8][4];
  ZERO_ACC();
  STAGE1_LOOP(w1h);

  uint32_t thi[4][4], tlo[4][4];
  T_EPILOGUE_MSG(sb1);

  ZERO_ACC();
#pragma unroll
  for (int kc = 0; kc < 4; kc++) STAGE2_CHUNK(w2h, kc);

  int row0 = rb + r0w + g, row1 = row0 + 8;
  M_EPILOGUE(sb2);
}

// ---------------------------------------------------------------------------
// upd: t = relu(h @ W1a + agg'' + b1); hn = t @ W2 + b2; bn; h = relu(hn+h)
// Standalone (last layer). ONE barrier.
// ---------------------------------------------------------------------------
__global__ void __launch_bounds__(256, 2) upd_kernel(
    const __half* __restrict__ wh, const __half* __restrict__ wl,
    const float* __restrict__ B1, const float* __restrict__ B2,
    const float* __restrict__ Gm, const float* __restrict__ Bt,
    const float* __restrict__ Mn, const float* __restrict__ Vr, int N) {
  extern __shared__ char smc[];
  __half* a_hi = (__half*)smc;       // 128 x 72
  __half* a_lo = a_hi + 128 * 72;
  __half* w1h = a_lo + 128 * 72;     // W1a
  __half* w1l = w1h + 64 * 72;
  __half* w2h = w1l + 64 * 72;       // W2
  __half* w2l = w2h + 64 * 72;
  __shared__ float sb1[64], b2s[64], scs[64], shs[64];

  int tid = threadIdx.x;
  int rb = blockIdx.x * 128;

  STAGE_W(w1h, w1l, wh, wl);
  STAGE_W(w2h, w2l, wh + 4096, wl + 4096);
  STAGE_A();
  if (tid < 64) {
    float s = __ldg(Gm + tid) * rsqrtf(__ldg(Vr + tid) + 1e-5f);
    scs[tid] = s;
    shs[tid] = __ldg(Bt + tid) - __ldg(Mn + tid) * s;
    sb1[tid] = __ldg(B1 + tid);
    b2s[tid] = __ldg(B2 + tid);
  }
  __syncthreads();

  FRAG_SETUP();
  float acc[8][4];
  ZERO_ACC();
  STAGE1_LOOP(w1h);

  int row0 = rb + r0w + g, row1 = row0 + 8;
  const float* aggp = (const float*)g_agg4f;

  // t = relu(acc + agg'' + b1) -> split fragments
  uint32_t thi[4][4], tlo[4][4];
#pragma unroll
  for (int j = 0; j < 8; j++) {
    int cA = 8 * j + 2 * tg;
    float2 ag01 = (row0 < N)
                      ? *(const float2*)(aggp + (size_t)row0 * 64 + cA)
                      : make_float2(0.f, 0.f);
    float2 ag23 = (row1 < N)
                      ? *(const float2*)(aggp + (size_t)row1 * 64 + cA)
                      : make_float2(0.f, 0.f);
    float f0 = fmaxf(acc[j][0] + ag01.x + sb1[cA], 0.f);
    float f1 = fmaxf(acc[j][1] + ag01.y + sb1[cA + 1], 0.f);
    float f2 = fmaxf(acc[j][2] + ag23.x + sb1[cA], 0.f);
    float f3 = fmaxf(acc[j][3] + ag23.y + sb1[cA + 1], 0.f);
    int kc = j >> 1, o = (j & 1) * 2;
    splitpack2(f0, f1, thi[kc][o], tlo[kc][o]);
    splitpack2(f2, f3, thi[kc][o + 1], tlo[kc][o + 1]);
  }

  ZERO_ACC();
#pragma unroll
  for (int kc = 0; kc < 4; kc++) STAGE2_CHUNK(w2h, kc);

  // h = relu(bn(acc + b2) + h_old); write split h back.
#pragma unroll
  for (int j = 0; j < 8; j++) {
    int cA = 8 * j + 2 * tg;
    if (row0 < N) {
      __half2 hh = *(const __half2*)((const __half*)g_hh4 +
                                     (size_t)row0 * 64 + cA);
      __half2 hl = *(const __half2*)((const __half*)g_hl4 +
                                     (size_t)row0 * 64 + cA);
      float2 fh = __half22float2(hh), fl = __half22float2(hl);
      float v0 = acc[j][0] + b2s[cA];
      float v1 = acc[j][1] + b2s[cA + 1];
      float o0 = fmaxf(fmaf(v0, scs[cA], shs[cA]) + fh.x + fl.x, 0.f);
      float o1 =
          fmaxf(fmaf(v1, scs[cA + 1], shs[cA + 1]) + fh.y + fl.y, 0.f);
      uint32_t ph, pl;
      splitpack2(o0, o1, ph, pl);
      *(uint32_t*)((__half*)g_hh4 + (size_t)row0 * 64 + cA) = ph;
      *(uint32_t*)((__half*)g_hl4 + (size_t)row0 * 64 + cA) = pl;
    }
    if (row1 < N) {
      __half2 hh = *(const __half2*)((const __half*)g_hh4 +
                                     (size_t)row1 * 64 + cA);
      __half2 hl = *(const __half2*)((const __half*)g_hl4 +
                                     (size_t)row1 * 64 + cA);
      float2 fh = __half22float2(hh), fl = __half22float2(hl);
      float v2 = acc[j][2] + b2s[cA];
      float v3 = acc[j][3] + b2s[cA + 1];
      float o2 = fmaxf(fmaf(v2, scs[cA], shs[cA]) + fh.x + fl.x, 0.f);
      float o3 =
          fmaxf(fmaf(v3, scs[cA + 1], shs[cA + 1]) + fh.y + fl.y, 0.f);
      uint32_t ph, pl;
      splitpack2(o2, o3, ph, pl);
      *(uint32_t*)((__half*)g_hh4 + (size_t)row1 * 64 + cA) = ph;
      *(uint32_t*)((__half*)g_hl4 + (size_t)row1 * 64 + cA) = pl;
    }
  }
}

// ---------------------------------------------------------------------------
// fused upd(l) + msg(l+1): four register-chained GEMM stages.
//   t1 = relu(h@uW1a + agg + b1u); hn = t1@uW2; h' = relu(bn(hn+b2u)+h);
//   (h' written to global, fragments kept)
//   t2 = relu(h'@mW1 + b1m); M'' = t2@V + c.
// ---------------------------------------------------------------------------
__global__ void __launch_bounds__(256, 2) fused_um_kernel(
    const __half* __restrict__ whu, const __half* __restrict__ wlu,
    const __half* __restrict__ whm, const __half* __restrict__ wlm,
    const float* __restrict__ B1u, const float* __restrict__ B2u,
    const float* __restrict__ Gm, const float* __restrict__ Bt,
    const float* __restrict__ Mn, const float* __restrict__ Vr,
    const float* __restrict__ B1m, const float* __restrict__ CBm, int N) {
  extern __shared__ char smc[];
  __half* a_hi = (__half*)smc;       // 128 x 72
  __half* a_lo = a_hi + 128 * 72;
  __half* u1h = a_lo + 128 * 72;     // updW1a
  __half* u1l = u1h + 64 * 72;
  __half* u2h = u1l + 64 * 72;       // updW2
  __half* u2l = u2h + 64 * 72;
  __half* m1h = u2l + 64 * 72;       // msgW1 (l+1)
  __half* m1l = m1h + 64 * 72;
  __half* vvh = m1l + 64 * 72;       // V (l+1)
  __half* vvl = vvh + 64 * 72;
  __shared__ float sb1u[64], b2u[64], scs[64], shs[64], sb1m[64], cbm[64];

  int tid = threadIdx.x;
  int rb = blockIdx.x * 128;

  STAGE_W(u1h, u1l, whu, wlu);
  STAGE_W(u2h, u2l, whu + 4096, wlu + 4096);
  STAGE_W(m1h, m1l, whm, wlm);
  STAGE_W(vvh, vvl, whm + 4096, wlm + 4096);
  STAGE_A();
  if (tid < 64) {
    float s = __ldg(Gm + tid) * rsqrtf(__ldg(Vr + tid) + 1e-5f);
    scs[tid] = s;
    shs[tid] = __ldg(Bt + tid) - __ldg(Mn + tid) * s;
    sb1u[tid] = __ldg(B1u + tid);
    b2u[tid] = __ldg(B2u + tid);
    sb1m[tid] = __ldg(B1m + tid);
    cbm[tid] = __ldg(CBm + tid);
  }
  __syncthreads();

  FRAG_SETUP();
  float acc[8][4];
  ZERO_ACC();
  STAGE1_LOOP(u1h);

  int row0 = rb + r0w + g, row1 = row0 + 8;
  const float* aggp = (const float*)g_agg4f;

  // t1 = relu(acc + agg'' + b1u) -> split fragments
  uint32_t thi[4][4], tlo[4][4];
#pragma unroll
  for (int j = 0; j < 8; j++) {
    int cA = 8 * j + 2 * tg;
    float2 ag01 = (row0 < N)
                      ? *(const float2*)(aggp + (size_t)row0 * 64 + cA)
                      : make_float2(0.f, 0.f);
    float2 ag23 = (row1 < N)
                      ? *(const float2*)(aggp + (size_t)row1 * 64 + cA)
                      : make_float2(0.f, 0.f);
    float f0 = fmaxf(acc[j][0] + ag01.x + sb1u[cA], 0.f);
    float f1 = fmaxf(acc[j][1] + ag01.y + sb1u[cA + 1], 0.f);
    float f2 = fmaxf(acc[j][2] + ag23.x + sb1u[cA], 0.f);
    float f3 = fmaxf(acc[j][3] + ag23.y + sb1u[cA + 1], 0.f);
    int kc = j >> 1, o = (j & 1) * 2;
    splitpack2(f0, f1, thi[kc][o], tlo[kc][o]);
    splitpack2(f2, f3, thi[kc][o + 1], tlo[kc][o + 1]);
  }

  ZERO_ACC();
#pragma unroll
  for (int kc = 0; kc < 4; kc++) STAGE2_CHUNK(u2h, kc);

  // h' epilogue: write split h' to global, keep fragments in thi/tlo.
#pragma unroll
  for (int j = 0; j < 8; j++) {
    int cA = 8 * j + 2 * tg;
    float2 fh0 = make_float2(0.f, 0.f), fl0 = make_float2(0.f, 0.f);
    float2 fh1 = make_float2(0.f, 0.f), fl1 = make_float2(0.f, 0.f);
    if (row0 < N) {
      fh0 = __half22float2(*(const __half2*)((const __half*)g_hh4 +
                                             (size_t)row0 * 64 + cA));
      fl0 = __half22float2(*(const __half2*)((const __half*)g_hl4 +
                                             (size_t)row0 * 64 + cA));
    }
    if (row1 < N) {
      fh1 = __half22float2(*(const __half2*)((const __half*)g_hh4 +
                                             (size_t)row1 * 64 + cA));
      fl1 = __half22float2(*(const __half2*)((const __half*)g_hl4 +
                                             (size_t)row1 * 64 + cA));
    }
    float o0 = fmaxf(
        fmaf(acc[j][0] + b2u[cA], scs[cA], shs[cA]) + fh0.x + fl0.x, 0.f);
    float o1 = fmaxf(fmaf(acc[j][1] + b2u[cA + 1], scs[cA + 1],
                          shs[cA + 1]) + fh0.y + fl0.y, 0.f);
    float o2 = fmaxf(
        fmaf(acc[j][2] + b2u[cA], scs[cA], shs[cA]) + fh1.x + fl1.x, 0.f);
    float o3 = fmaxf(fmaf(acc[j][3] + b2u[cA + 1], scs[cA + 1],
                          shs[cA + 1]) + fh1.y + fl1.y, 0.f);
    uint32_t ph0, pl0, ph1, pl1;
    splitpack2(o0, o1, ph0, pl0);
    splitpack2(o2, o3, ph1, pl1);
    if (row0 < N) {
      *(uint32_t*)((__half*)g_hh4 + (size_t)row0 * 64 + cA) = ph0;
      *(uint32_t*)((__half*)g_hl4 + (size_t)row0 * 64 + cA) = pl0;
    }
    if (row1 < N) {
      *(uint32_t*)((__half*)g_hh4 + (size_t)row1 * 64 + cA) = ph1;
      *(uint32_t*)((__half*)g_hl4 + (size_t)row1 * 64 + cA) = pl1;
    }
    int kc = j >> 1, o = (j & 1) * 2;
    thi[kc][o] = ph0;
    tlo[kc][o] = pl0;
    thi[kc][o + 1] = ph1;
    tlo[kc][o + 1] = pl1;
  }

  // msg stage 1: acc = h' @ mW1 (h' fragments in thi/tlo)
  ZERO_ACC();
#pragma unroll
  for (int kc = 0; kc < 4; kc++) STAGE2_CHUNK(m1h, kc);

  // t2 = relu(acc + b1m) -> fragments
  T_EPILOGUE_MSG(sb1m);

  // msg stage 2: acc = t2 @ V
  ZERO_ACC();
#pragma unroll
  for (int kc = 0; kc < 4; kc++) STAGE2_CHUNK(vvh, kc);

  M_EPILOGUE(cbm);
}

// ---------------------------------------------------------------------------
// out = relu(h[:NQ] @ out_w1 + b1) @ out_w2 + b2   (warp per node)
// ---------------------------------------------------------------------------
__global__ void __launch_bounds__(256) out_kernel(
    const float* __restrict__ w1, const float* __restrict__ b1,
    const float* __restrict__ w2, const float* __restrict__ b2,
    float* __restrict__ out, int NQ) {
  int warp = (blockIdx.x * blockDim.x + threadIdx.x) >> 5;
  int lane = threadIdx.x & 31;
  if (warp >= NQ) return;
  float2 hh = __half22float2(((const __half2*)g_hh4)[(size_t)warp * 32 + lane]);
  float2 hl = __half22float2(((const __half2*)g_hl4)[(size_t)warp * 32 + lane]);
  float2 hv = make_float2(hh.x + hl.x, hh.y + hl.y);
  float acc = __ldg(b1 + lane);
#pragma unroll
  for (int kk = 0; kk < 32; kk++) {
    float hx = __shfl_sync(0xffffffffu, hv.x, kk);
    float hy = __shfl_sync(0xffffffffu, hv.y, kk);
    acc = fmaf(hx, __ldg(w1 + (2 * kk) * 32 + lane), acc);
    acc = fmaf(hy, __ldg(w1 + (2 * kk + 1) * 32 + lane), acc);
  }
  float v = fmaxf(acc, 0.f) * __ldg(w2 + lane);
#pragma unroll
  for (int o = 16; o; o >>= 1) v += __shfl_down_sync(0xffffffffu, v, o);
  if (lane == 0) out[warp] = v + __ldg(b2);
}

// ---------------------------------------------------------------------------
extern "C" void kernel_launch(void* const* d_in, const int* in_sizes, int n_in,
                              void* d_out, int out_size) {
  int off = (n_in >= 21) ? 1 : 0;
  const float* x      = (const float*)d_in[0];
  const int*   ei     = (const int*)d_in[1];
  const float* w_in   = (const float*)d_in[2 + off];
  const float* b_in   = (const float*)d_in[3 + off];
  const float* msg_w1 = (const float*)d_in[4 + off];
  const float* msg_b1 = (const float*)d_in[5 + off];
  const float* msg_w2 = (const float*)d_in[6 + off];
  const float* msg_b2 = (const float*)d_in[7 + off];
  const float* upd_w1 = (const float*)d_in[8 + off];
  const float* upd_b1 = (const float*)d_in[9 + off];
  const float* upd_w2 = (const float*)d_in[10 + off];
  const float* upd_b2 = (const float*)d_in[11 + off];
  const float* bn_g   = (const float*)d_in[12 + off];
  const float* bn_b   = (const float*)d_in[13 + off];
  const float* bn_m   = (const float*)d_in[14 + off];
  const float* bn_v   = (const float*)d_in[15 + off];
  const float* out_w1 = (const float*)d_in[16 + off];
  const float* out_b1 = (const float*)d_in[17 + off];
  const float* out_w2 = (const float*)d_in[18 + off];
  const float* out_b2 = (const float*)d_in[19 + off];

  int N = in_sizes[0] / 3;
  int E = in_sizes[1] / 2;
  int L = in_sizes[4 + off] / (64 * 64);
  int NQ = out_size;

  const int GEMM_SMEM = (2 * 128 * 72 + 4 * 64 * 72) * 2;   // 73,728 B
  const int FUSE_SMEM = (2 * 128 * 72 + 8 * 64 * 72) * 2;   // 110,592 B
  cudaFuncSetAttribute(msg_kernel, cudaFuncAttributeMaxDynamicSharedMemorySize,
                       GEMM_SMEM);
  cudaFuncSetAttribute(upd_kernel, cudaFuncAttributeMaxDynamicSharedMemorySize,
                       GEMM_SMEM);
  cudaFuncSetAttribute(fused_um_kernel,
                       cudaFuncAttributeMaxDynamicSharedMemorySize, FUSE_SMEM);

  int gb = (N + 127) / 128;
  int nb_scan = (N + 1023) / 1024;

  void* whp = nullptr;
  void* wlp = nullptr;
  void* cbp = nullptr;
  cudaGetSymbolAddress(&whp, g_wh4);
  cudaGetSymbolAddress(&wlp, g_wl4);
  cudaGetSymbolAddress(&cbp, g_cb);
  const __half* wh = (const __half*)whp;
  const __half* wl = (const __half*)wlp;
  const float* cb = (const float*)cbp;

  // Order: wsplit(1), wfuse(2), input(3), msg0(4) <- profiled slot, ...
  wprep_split_kernel<<<(L * 12288 + 255) / 256, 256>>>(msg_w1, upd_w1, upd_w2,
                                                       L);
  wprep_fuse_kernel<<<L, 256>>>(msg_w2, upd_w1, msg_b2);
  input_kernel<<<(N * 64 + 255) / 256, 256>>>(x, w_in, b_in, N);
  msg_kernel<<<gb, 256, GEMM_SMEM>>>(wh, wl, msg_b1, cb, N);
  zero_counts_kernel<<<(N + 255) / 256, 256>>>(N);
  hist_kernel<<<(E + 255) / 256, 256>>>(ei, E);
  scan1_kernel<<<nb_scan, 1024>>>(N);
  scan2_kernel<<<1, 128>>>(nb_scan);
  scan3_kernel<<<(N + 255) / 256, 256>>>(N);
  fill_kernel<<<(E + 255) / 256, 256>>>(ei, E);

  for (int l = 0; l < L; l++) {
    gather_kernel<<<(N * 32 + 255) / 256, 256>>>(N);
    if (l + 1 < L) {
      fused_um_kernel<<<gb, 256, FUSE_SMEM>>>(
          wh + l * 16384 + 8192, wl + l * 16384 + 8192,
          wh + (l + 1) * 16384, wl + (l + 1) * 16384,
          upd_b1 + l * 64, upd_b2 + l * 64, bn_g + l * 64, bn_b + l * 64,
          bn_m + l * 64, bn_v + l * 64, msg_b1 + (l + 1) * 64,
          cb + (l + 1) * 64, N);
    } else {
      upd_kernel<<<gb, 256, GEMM_SMEM>>>(
          wh + l * 16384 + 8192, wl + l * 16384 + 8192, upd_b1 + l * 64,
          upd_b2 + l * 64, bn_g + l * 64, bn_b + l * 64, bn_m + l * 64,
          bn_v + l * 64, N);
    }
  }

  out_kernel<<<(NQ * 32 + 255) / 256, 256>>>(out_w1, out_b1, out_w2, out_b2,
                                             (float*)d_out, NQ);
}